// round 1
// baseline (speedup 1.0000x reference)
#include <cuda_runtime.h>
#include <math.h>
#include <float.h>

#define S_LEN 2048
#define HID   2048
#define NHEAD 16
#define HS    128

// ---- scratch (no cudaMalloc allowed) ----
__device__ float g_q[NHEAD * S_LEN * HS];
__device__ float g_k[NHEAD * S_LEN * HS];
__device__ float g_v[NHEAD * S_LEN * HS];
__device__ float g_ctx[S_LEN * HID];

// =====================================================================
// Tiled SGEMM: C = A[M,K] @ B[K,N] + bias
// MODE 0: A = hidden, scatter output into g_q/g_k/g_v (head-major)
// MODE 1: A = g_ctx,  plain output to C
// BM=BN=128, BK=16, 256 threads, 8x8 per thread
// =====================================================================
template<int MODE>
__global__ void __launch_bounds__(256) gemm_kernel(const float* __restrict__ A_in,
                                                   const float* __restrict__ B,
                                                   const float* __restrict__ bias,
                                                   float* __restrict__ C,
                                                   int M, int N, int K)
{
    const int BM = 128, BN = 128, BK = 16;
    __shared__ float As[BK][BM + 4];   // transposed A tile, padded
    __shared__ float Bs[BK][BN];

    const float* A = (MODE == 1) ? g_ctx : A_in;

    int tid  = threadIdx.x;
    int brow = blockIdx.y * BM;
    int bcol = blockIdx.x * BN;
    int ty = tid >> 4, tx = tid & 15;

    int a_row = tid >> 2;           // 0..63 (+64 second batch)
    int a_col = (tid & 3) << 2;     // 0,4,8,12
    int b_row = tid >> 5;           // 0..7  (+8 second batch)
    int b_col = (tid & 31) << 2;

    float acc[8][8];
#pragma unroll
    for (int i = 0; i < 8; i++)
#pragma unroll
        for (int j = 0; j < 8; j++) acc[i][j] = 0.f;

    for (int k0 = 0; k0 < K; k0 += BK) {
#pragma unroll
        for (int i = 0; i < 2; i++) {
            int r = a_row + i * 64;
            float4 v = *(const float4*)(A + (size_t)(brow + r) * K + k0 + a_col);
            As[a_col + 0][r] = v.x;
            As[a_col + 1][r] = v.y;
            As[a_col + 2][r] = v.z;
            As[a_col + 3][r] = v.w;
        }
#pragma unroll
        for (int i = 0; i < 2; i++) {
            int r = b_row + i * 8;
            *(float4*)(&Bs[r][b_col]) =
                *(const float4*)(B + (size_t)(k0 + r) * N + bcol + b_col);
        }
        __syncthreads();
#pragma unroll
        for (int k = 0; k < BK; k++) {
            float rm[8], rn[8];
            *(float4*)&rm[0] = *(float4*)&As[k][ty * 8];
            *(float4*)&rm[4] = *(float4*)&As[k][ty * 8 + 4];
            *(float4*)&rn[0] = *(float4*)&Bs[k][tx * 8];
            *(float4*)&rn[4] = *(float4*)&Bs[k][tx * 8 + 4];
#pragma unroll
            for (int i = 0; i < 8; i++)
#pragma unroll
                for (int j = 0; j < 8; j++)
                    acc[i][j] = fmaf(rm[i], rn[j], acc[i][j]);
        }
        __syncthreads();
    }

    if (MODE == 0) {
        // whole 128-wide tile belongs to one (kind, head)
        int kind = bcol / HID;
        int rem  = bcol % HID;
        int head = rem / HS;
        float* dst = (kind == 0 ? g_q : kind == 1 ? g_k : g_v) + (size_t)head * S_LEN * HS;
#pragma unroll
        for (int i = 0; i < 8; i++) {
            int r = brow + ty * 8 + i;
#pragma unroll
            for (int j = 0; j < 8; j += 4) {
                int d = tx * 8 + j;     // col within head (tile-local == head-local)
                float4 v;
                v.x = acc[i][j + 0] + bias[bcol + d + 0];
                v.y = acc[i][j + 1] + bias[bcol + d + 1];
                v.z = acc[i][j + 2] + bias[bcol + d + 2];
                v.w = acc[i][j + 3] + bias[bcol + d + 3];
                *(float4*)(dst + (size_t)r * HS + d) = v;
            }
        }
    } else {
#pragma unroll
        for (int i = 0; i < 8; i++) {
            int r = brow + ty * 8 + i;
#pragma unroll
            for (int j = 0; j < 8; j += 4) {
                int c = bcol + tx * 8 + j;
                float4 v;
                v.x = acc[i][j + 0] + bias[c + 0];
                v.y = acc[i][j + 1] + bias[c + 1];
                v.z = acc[i][j + 2] + bias[c + 2];
                v.w = acc[i][j + 3] + bias[c + 3];
                *(float4*)(C + (size_t)r * N + c) = v;
            }
        }
    }
}

// =====================================================================
// Flash attention (fp32, causal), per block: 1 head x 64 query rows.
// BM=BN=64, 256 threads. Online softmax. O in registers (4x8/thread).
// smem: Qt[128][68] (Q^T), KV union (K^T [128][68] | V [64][128]),
//       Ss[64][65], row stats. Total ~87 KB dynamic.
// =====================================================================
#define ABM 64
#define ABN 64
#define KT_STRIDE 68
#define SS_STRIDE 65

__global__ void __launch_bounds__(256) attn_kernel()
{
    extern __shared__ float sm[];
    float* Qt = sm;                               // 128*68
    float* KV = Qt + 128 * KT_STRIDE;             // max(128*68, 64*128) = 8704
    float* Ss = KV + 128 * KT_STRIDE;             // 64*65
    float* row_m     = Ss + 64 * SS_STRIDE;
    float* row_l     = row_m + 64;
    float* row_scale = row_l + 64;

    int tid   = threadIdx.x;
    int qtile = blockIdx.x;          // 0..31
    int head  = blockIdx.y;          // 0..15
    const float* Q  = g_q + (size_t)head * S_LEN * HS;
    const float* Kp = g_k + (size_t)head * S_LEN * HS;
    const float* Vp = g_v + (size_t)head * S_LEN * HS;

    int q0 = qtile * ABM;

    // load Q tile transposed: Qt[d][r]
#pragma unroll
    for (int it = 0; it < 8; it++) {
        int idx = tid + it * 256;        // 0..2047 float4 slots
        int r = idx >> 5;
        int c = (idx & 31) << 2;
        float4 v = *(const float4*)(Q + (size_t)(q0 + r) * HS + c);
        Qt[(c + 0) * KT_STRIDE + r] = v.x;
        Qt[(c + 1) * KT_STRIDE + r] = v.y;
        Qt[(c + 2) * KT_STRIDE + r] = v.z;
        Qt[(c + 3) * KT_STRIDE + r] = v.w;
    }
    if (tid < 64) { row_m[tid] = -FLT_MAX; row_l[tid] = 0.f; }

    int ty = tid >> 4, tx = tid & 15;
    float o[4][8];
#pragma unroll
    for (int i = 0; i < 4; i++)
#pragma unroll
        for (int j = 0; j < 8; j++) o[i][j] = 0.f;

    const float scale = 0.08838834764831845f;    // 1/sqrt(128)

    for (int jt = 0; jt <= qtile; jt++) {
        int k0 = jt * ABN;
        __syncthreads();   // prev PV done / Q loaded before KV overwrite

        // load K tile transposed: KV[d][r]
#pragma unroll
        for (int it = 0; it < 8; it++) {
            int idx = tid + it * 256;
            int r = idx >> 5;
            int c = (idx & 31) << 2;
            float4 v = *(const float4*)(Kp + (size_t)(k0 + r) * HS + c);
            KV[(c + 0) * KT_STRIDE + r] = v.x;
            KV[(c + 1) * KT_STRIDE + r] = v.y;
            KV[(c + 2) * KT_STRIDE + r] = v.z;
            KV[(c + 3) * KT_STRIDE + r] = v.w;
        }
        __syncthreads();

        // S = Q @ K^T  (4x4 per thread)
        float s4[4][4];
#pragma unroll
        for (int i = 0; i < 4; i++)
#pragma unroll
            for (int j = 0; j < 4; j++) s4[i][j] = 0.f;
#pragma unroll 4
        for (int k = 0; k < HS; k++) {
            float qv[4], kv[4];
            *(float4*)qv = *(float4*)&Qt[k * KT_STRIDE + ty * 4];
            *(float4*)kv = *(float4*)&KV[k * KT_STRIDE + tx * 4];
#pragma unroll
            for (int i = 0; i < 4; i++)
#pragma unroll
                for (int j = 0; j < 4; j++)
                    s4[i][j] = fmaf(qv[i], kv[j], s4[i][j]);
        }

        bool diag = (jt == qtile);
#pragma unroll
        for (int i = 0; i < 4; i++) {
            int r = ty * 4 + i;
#pragma unroll
            for (int j = 0; j < 4; j++) {
                int c = tx * 4 + j;
                float val = s4[i][j] * scale;
                if (diag && c > r) val = -FLT_MAX;   // strict causal == additive -65504
                Ss[r * SS_STRIDE + c] = val;
            }
        }
        __syncthreads();

        // load V tile (overwrites KV) — concurrent with softmax (touches Ss only)
#pragma unroll
        for (int it = 0; it < 8; it++) {
            int idx = tid + it * 256;
            int r = idx >> 5;
            int c = (idx & 31) << 2;
            *(float4*)(KV + r * HS + c) =
                *(const float4*)(Vp + (size_t)(k0 + r) * HS + c);
        }

        // online softmax, one row per thread (threads 0..63)
        if (tid < 64) {
            int r = tid;
            float mold = row_m[r];
            float mx = mold;
#pragma unroll 8
            for (int c = 0; c < ABN; c++) mx = fmaxf(mx, Ss[r * SS_STRIDE + c]);
            float sc = __expf(mold - mx);
            float sum = 0.f;
#pragma unroll 8
            for (int c = 0; c < ABN; c++) {
                float p = __expf(Ss[r * SS_STRIDE + c] - mx);
                Ss[r * SS_STRIDE + c] = p;
                sum += p;
            }
            row_l[r] = row_l[r] * sc + sum;
            row_m[r] = mx;
            row_scale[r] = sc;
        }
        __syncthreads();

        // rescale O, then O += P @ V
        float rs[4];
#pragma unroll
        for (int i = 0; i < 4; i++) rs[i] = row_scale[ty * 4 + i];
#pragma unroll
        for (int i = 0; i < 4; i++)
#pragma unroll
            for (int j = 0; j < 8; j++) o[i][j] *= rs[i];

#pragma unroll 4
        for (int k = 0; k < ABN; k++) {
            float pv[4];
#pragma unroll
            for (int i = 0; i < 4; i++) pv[i] = Ss[(ty * 4 + i) * SS_STRIDE + k];
            float vv[8];
            *(float4*)&vv[0] = *(float4*)&KV[k * HS + tx * 8];
            *(float4*)&vv[4] = *(float4*)&KV[k * HS + tx * 8 + 4];
#pragma unroll
            for (int i = 0; i < 4; i++)
#pragma unroll
                for (int j = 0; j < 8; j++)
                    o[i][j] = fmaf(pv[i], vv[j], o[i][j]);
        }
    }
    __syncthreads();

    // epilogue: normalize and write ctx[s][head*128 + d]
#pragma unroll
    for (int i = 0; i < 4; i++) {
        int r = ty * 4 + i;
        float inv = 1.f / row_l[r];
        float* dst = g_ctx + (size_t)(q0 + r) * HID + head * HS + tx * 8;
        float4 v0 = make_float4(o[i][0] * inv, o[i][1] * inv, o[i][2] * inv, o[i][3] * inv);
        float4 v1 = make_float4(o[i][4] * inv, o[i][5] * inv, o[i][6] * inv, o[i][7] * inv);
        *(float4*)dst       = v0;
        *(float4*)(dst + 4) = v1;
    }
}

// =====================================================================
// launch
// =====================================================================
extern "C" void kernel_launch(void* const* d_in, const int* in_sizes, int n_in,
                              void* d_out, int out_size)
{
    const float* hidden  = (const float*)d_in[0];
    // d_in[1] = ltor_mask (always causal tril; handled analytically)
    const float* W_qkv   = (const float*)d_in[2];
    const float* b_qkv   = (const float*)d_in[3];
    const float* W_dense = (const float*)d_in[4];
    const float* b_dense = (const float*)d_in[5];
    float* out = (float*)d_out;

    const int ATTN_SMEM = (128 * KT_STRIDE + 128 * KT_STRIDE + 64 * SS_STRIDE + 192)
                          * (int)sizeof(float);   // 87808 B
    cudaFuncSetAttribute(attn_kernel,
                         cudaFuncAttributeMaxDynamicSharedMemorySize, ATTN_SMEM);

    // 1) QKV projection, scatter into head-major Q/K/V
    dim3 g1(6144 / 128, 2048 / 128);
    gemm_kernel<0><<<g1, 256>>>(hidden, W_qkv, b_qkv, nullptr, 2048, 6144, 2048);

    // 2) causal flash attention -> g_ctx
    attn_kernel<<<dim3(32, 16), 256, ATTN_SMEM>>>();

    // 3) dense projection: out = g_ctx @ W_dense + b_dense
    dim3 g3(2048 / 128, 2048 / 128);
    gemm_kernel<1><<<g3, 256>>>(nullptr, W_dense, b_dense, out, 2048, 2048, 2048);
}

// round 3
// speedup vs baseline: 1.7089x; 1.7089x over previous
#include <cuda_runtime.h>
#include <math.h>
#include <float.h>
#include <stdint.h>

#define S_LEN 2048
#define HID   2048
#define NHEAD 16
#define HS    128

// ---- scratch (no cudaMalloc allowed) ----
__device__ float g_q[NHEAD * S_LEN * HS];
__device__ float g_k[NHEAD * S_LEN * HS];
__device__ float g_v[NHEAD * S_LEN * HS];
__device__ float g_ctx[S_LEN * HID];          // tf32-rounded fp32
__device__ float g_a[S_LEN * HID];            // hidden, tf32-rounded
__device__ float g_wt_qkv[3 * HID * HID];     // W_qkv^T  [6144, 2048] tf32
__device__ float g_wt_dense[HID * HID];       // W_dense^T [2048, 2048] tf32

__device__ __forceinline__ float to_tf32(float x) {
    float r; asm("cvt.rna.tf32.f32 %0, %1;" : "=f"(r) : "f"(x)); return r;
}

// m16n8k8 tf32 mma (sm_80+ legacy path; valid on PTX target sm_103)
__device__ __forceinline__ void mma_tf32(float* d, const uint32_t* a,
                                         const uint32_t* b, const float* c) {
    asm volatile(
        "mma.sync.aligned.m16n8k8.row.col.f32.tf32.tf32.f32 "
        "{%0, %1, %2, %3}, {%4, %5, %6, %7}, {%8, %9}, {%10, %11, %12, %13};"
        : "=f"(d[0]), "=f"(d[1]), "=f"(d[2]), "=f"(d[3])
        : "r"(a[0]), "r"(a[1]), "r"(a[2]), "r"(a[3]),
          "r"(b[0]), "r"(b[1]),
          "f"(c[0]), "f"(c[1]), "f"(c[2]), "f"(c[3]));
}

// =====================================================================
// prep kernels
// =====================================================================
__global__ void __launch_bounds__(256) cvt_tf32_kernel(const float* __restrict__ in) {
    int i = blockIdx.x * blockDim.x + threadIdx.x;
    float4 v = ((const float4*)in)[i];
    v.x = to_tf32(v.x); v.y = to_tf32(v.y); v.z = to_tf32(v.z); v.w = to_tf32(v.w);
    ((float4*)g_a)[i] = v;
}

// W [K, N] fp32 -> Wt [N, K] tf32
template<int WHICH>
__global__ void __launch_bounds__(256) transpose_tf32_kernel(const float* __restrict__ W,
                                                             int K, int N) {
    __shared__ float t[32][33];
    float* Wt = (WHICH == 0) ? g_wt_qkv : g_wt_dense;
    int n0 = blockIdx.x * 32, k0 = blockIdx.y * 32;
    int tx = threadIdx.x & 31, ty = threadIdx.x >> 5;
#pragma unroll
    for (int i = 0; i < 32; i += 8)
        t[ty + i][tx] = W[(size_t)(k0 + ty + i) * N + n0 + tx];
    __syncthreads();
#pragma unroll
    for (int i = 0; i < 32; i += 8)
        Wt[(size_t)(n0 + ty + i) * K + k0 + tx] = to_tf32(t[tx][ty + i]);
}

// =====================================================================
// tf32 tensor GEMM via mma.sync: D[M,N] = A[M,K] @ Bt[N,K]^T + bias
// block 128x128x32, 256 thr (8 warps 2x4), warp tile 64x32 (4x4 m16n8k8)
// MODE 0: A = g_a, B = g_wt_qkv, scatter into g_q/g_k/g_v (head-major)
// MODE 1: A = g_ctx, B = g_wt_dense, write C
// =====================================================================
#define SMS 36   // smem row stride (floats): conflict-free fragment loads

template<int MODE>
__global__ void __launch_bounds__(256)
tc_gemm(const float* __restrict__ bias, float* __restrict__ C, int K, int N)
{
    __shared__ float As[128 * SMS];
    __shared__ float Bs[128 * SMS];

    const float* A  = (MODE == 0) ? g_a : g_ctx;
    const float* Bt = (MODE == 0) ? g_wt_qkv : g_wt_dense;

    int tid  = threadIdx.x;
    int lane = tid & 31, wid = tid >> 5;
    int bcol = blockIdx.x * 128;
    int brow = blockIdx.y * 128;
    int wm = (wid >> 2) * 64;      // warp row offset in tile
    int wn = (wid & 3) * 32;       // warp col offset in tile

    int g = lane >> 2;             // group id 0..7
    int t = lane & 3;              // thread-in-group 0..3

    float acc[4][4][4];
#pragma unroll
    for (int mt = 0; mt < 4; mt++)
#pragma unroll
        for (int nt = 0; nt < 4; nt++)
#pragma unroll
            for (int r = 0; r < 4; r++) acc[mt][nt][r] = 0.f;

    for (int k0 = 0; k0 < K; k0 += 32) {
        // stage A[128][32] and B[128][32] (both row-major, row stride K)
#pragma unroll
        for (int it = 0; it < 4; it++) {
            int idx = tid + it * 256;          // 0..1023 float4 slots
            int row = idx >> 3;
            int c4  = (idx & 7) << 2;
            *(float4*)&As[row * SMS + c4] =
                *(const float4*)(A + (size_t)(brow + row) * K + k0 + c4);
            *(float4*)&Bs[row * SMS + c4] =
                *(const float4*)(Bt + (size_t)(bcol + row) * K + k0 + c4);
        }
        __syncthreads();

#pragma unroll
        for (int kk = 0; kk < 32; kk += 8) {
            uint32_t af[4][4], bf[4][2];
#pragma unroll
            for (int mt = 0; mt < 4; mt++) {
                const float* ap = &As[(wm + mt * 16 + g) * SMS + kk + t];
                af[mt][0] = __float_as_uint(ap[0]);
                af[mt][1] = __float_as_uint(ap[8 * SMS]);
                af[mt][2] = __float_as_uint(ap[4]);
                af[mt][3] = __float_as_uint(ap[8 * SMS + 4]);
            }
#pragma unroll
            for (int nt = 0; nt < 4; nt++) {
                const float* bp = &Bs[(wn + nt * 8 + g) * SMS + kk + t];
                bf[nt][0] = __float_as_uint(bp[0]);
                bf[nt][1] = __float_as_uint(bp[4]);
            }
#pragma unroll
            for (int mt = 0; mt < 4; mt++)
#pragma unroll
                for (int nt = 0; nt < 4; nt++)
                    mma_tf32(acc[mt][nt], af[mt], bf[nt], acc[mt][nt]);
        }
        __syncthreads();
    }

    // ---- epilogue ----
    // c frag: c0 (row g,   col 2t), c1 (row g,   col 2t+1)
    //         c2 (row g+8, col 2t), c3 (row g+8, col 2t+1)
    float* dstbase;
    int ld;
    if (MODE == 0) {
        int kind = bcol >> 11;
        int head = (bcol & 2047) >> 7;
        dstbase = (kind == 0 ? g_q : kind == 1 ? g_k : g_v)
                  + (size_t)head * S_LEN * HS;
        ld = HS;
    } else {
        dstbase = C;
        ld = N;
    }
#pragma unroll
    for (int mt = 0; mt < 4; mt++) {
#pragma unroll
        for (int nt = 0; nt < 4; nt++) {
            int col = wn + nt * 8 + 2 * t;           // col within 128-tile
            int bi  = bcol + col;
            float bx = __ldg(&bias[bi]), by = __ldg(&bias[bi + 1]);
            int r0 = brow + wm + mt * 16 + g;
            int cc = (MODE == 0) ? col : bcol + col;
            float2 v0 = make_float2(acc[mt][nt][0] + bx, acc[mt][nt][1] + by);
            float2 v1 = make_float2(acc[mt][nt][2] + bx, acc[mt][nt][3] + by);
            *(float2*)(dstbase + (size_t)r0 * ld + cc)       = v0;
            *(float2*)(dstbase + (size_t)(r0 + 8) * ld + cc) = v1;
        }
    }
}

// =====================================================================
// Flash attention (fp32, causal) — unchanged from passing R1 kernel,
// except epilogue stores tf32-rounded ctx (input to the tf32 dense GEMM).
// =====================================================================
#define ABM 64
#define ABN 64
#define KT_STRIDE 68
#define SS_STRIDE 65

__global__ void __launch_bounds__(256) attn_kernel()
{
    extern __shared__ float sm[];
    float* Qt = sm;
    float* KV = Qt + 128 * KT_STRIDE;
    float* Ss = KV + 128 * KT_STRIDE;
    float* row_m     = Ss + 64 * SS_STRIDE;
    float* row_l     = row_m + 64;
    float* row_scale = row_l + 64;

    int tid   = threadIdx.x;
    int qtile = blockIdx.x;
    int head  = blockIdx.y;
    const float* Q  = g_q + (size_t)head * S_LEN * HS;
    const float* Kp = g_k + (size_t)head * S_LEN * HS;
    const float* Vp = g_v + (size_t)head * S_LEN * HS;

    int q0 = qtile * ABM;

#pragma unroll
    for (int it = 0; it < 8; it++) {
        int idx = tid + it * 256;
        int r = idx >> 5;
        int c = (idx & 31) << 2;
        float4 v = *(const float4*)(Q + (size_t)(q0 + r) * HS + c);
        Qt[(c + 0) * KT_STRIDE + r] = v.x;
        Qt[(c + 1) * KT_STRIDE + r] = v.y;
        Qt[(c + 2) * KT_STRIDE + r] = v.z;
        Qt[(c + 3) * KT_STRIDE + r] = v.w;
    }
    if (tid < 64) { row_m[tid] = -FLT_MAX; row_l[tid] = 0.f; }

    int ty = tid >> 4, tx = tid & 15;
    float o[4][8];
#pragma unroll
    for (int i = 0; i < 4; i++)
#pragma unroll
        for (int j = 0; j < 8; j++) o[i][j] = 0.f;

    const float scale = 0.08838834764831845f;

    for (int jt = 0; jt <= qtile; jt++) {
        int k0 = jt * ABN;
        __syncthreads();

#pragma unroll
        for (int it = 0; it < 8; it++) {
            int idx = tid + it * 256;
            int r = idx >> 5;
            int c = (idx & 31) << 2;
            float4 v = *(const float4*)(Kp + (size_t)(k0 + r) * HS + c);
            KV[(c + 0) * KT_STRIDE + r] = v.x;
            KV[(c + 1) * KT_STRIDE + r] = v.y;
            KV[(c + 2) * KT_STRIDE + r] = v.z;
            KV[(c + 3) * KT_STRIDE + r] = v.w;
        }
        __syncthreads();

        float s4[4][4];
#pragma unroll
        for (int i = 0; i < 4; i++)
#pragma unroll
            for (int j = 0; j < 4; j++) s4[i][j] = 0.f;
#pragma unroll 4
        for (int k = 0; k < HS; k++) {
            float qv[4], kv[4];
            *(float4*)qv = *(float4*)&Qt[k * KT_STRIDE + ty * 4];
            *(float4*)kv = *(float4*)&KV[k * KT_STRIDE + tx * 4];
#pragma unroll
            for (int i = 0; i < 4; i++)
#pragma unroll
                for (int j = 0; j < 4; j++)
                    s4[i][j] = fmaf(qv[i], kv[j], s4[i][j]);
        }

        bool diag = (jt == qtile);
#pragma unroll
        for (int i = 0; i < 4; i++) {
            int r = ty * 4 + i;
#pragma unroll
            for (int j = 0; j < 4; j++) {
                int c = tx * 4 + j;
                float val = s4[i][j] * scale;
                if (diag && c > r) val = -FLT_MAX;
                Ss[r * SS_STRIDE + c] = val;
            }
        }
        __syncthreads();

#pragma unroll
        for (int it = 0; it < 8; it++) {
            int idx = tid + it * 256;
            int r = idx >> 5;
            int c = (idx & 31) << 2;
            *(float4*)(KV + r * HS + c) =
                *(const float4*)(Vp + (size_t)(k0 + r) * HS + c);
        }

        if (tid < 64) {
            int r = tid;
            float mold = row_m[r];
            float mx = mold;
#pragma unroll 8
            for (int c = 0; c < ABN; c++) mx = fmaxf(mx, Ss[r * SS_STRIDE + c]);
            float sc = __expf(mold - mx);
            float sum = 0.f;
#pragma unroll 8
            for (int c = 0; c < ABN; c++) {
                float p = __expf(Ss[r * SS_STRIDE + c] - mx);
                Ss[r * SS_STRIDE + c] = p;
                sum += p;
            }
            row_l[r] = row_l[r] * sc + sum;
            row_m[r] = mx;
            row_scale[r] = sc;
        }
        __syncthreads();

        float rs[4];
#pragma unroll
        for (int i = 0; i < 4; i++) rs[i] = row_scale[ty * 4 + i];
#pragma unroll
        for (int i = 0; i < 4; i++)
#pragma unroll
            for (int j = 0; j < 8; j++) o[i][j] *= rs[i];

#pragma unroll 4
        for (int k = 0; k < ABN; k++) {
            float pv[4];
#pragma unroll
            for (int i = 0; i < 4; i++) pv[i] = Ss[(ty * 4 + i) * SS_STRIDE + k];
            float vv[8];
            *(float4*)&vv[0] = *(float4*)&KV[k * HS + tx * 8];
            *(float4*)&vv[4] = *(float4*)&KV[k * HS + tx * 8 + 4];
#pragma unroll
            for (int i = 0; i < 4; i++)
#pragma unroll
                for (int j = 0; j < 8; j++)
                    o[i][j] = fmaf(pv[i], vv[j], o[i][j]);
        }
    }
    __syncthreads();

#pragma unroll
    for (int i = 0; i < 4; i++) {
        int r = ty * 4 + i;
        float inv = 1.f / row_l[r];
        float* dst = g_ctx + (size_t)(q0 + r) * HID + head * HS + tx * 8;
        float4 v0 = make_float4(to_tf32(o[i][0] * inv), to_tf32(o[i][1] * inv),
                                to_tf32(o[i][2] * inv), to_tf32(o[i][3] * inv));
        float4 v1 = make_float4(to_tf32(o[i][4] * inv), to_tf32(o[i][5] * inv),
                                to_tf32(o[i][6] * inv), to_tf32(o[i][7] * inv));
        *(float4*)dst       = v0;
        *(float4*)(dst + 4) = v1;
    }
}

// =====================================================================
// launch
// =====================================================================
extern "C" void kernel_launch(void* const* d_in, const int* in_sizes, int n_in,
                              void* d_out, int out_size)
{
    const float* hidden  = (const float*)d_in[0];
    // d_in[1] = ltor_mask (always causal tril; handled analytically)
    const float* W_qkv   = (const float*)d_in[2];
    const float* b_qkv   = (const float*)d_in[3];
    const float* W_dense = (const float*)d_in[4];
    const float* b_dense = (const float*)d_in[5];
    float* out = (float*)d_out;

    const int ATTN_SMEM = (128 * KT_STRIDE + 128 * KT_STRIDE + 64 * SS_STRIDE + 192)
                          * (int)sizeof(float);
    cudaFuncSetAttribute(attn_kernel,
                         cudaFuncAttributeMaxDynamicSharedMemorySize, ATTN_SMEM);

    // prep: tf32-round activations; transpose+round weights
    cvt_tf32_kernel<<<(S_LEN * HID / 4) / 256, 256>>>(hidden);
    transpose_tf32_kernel<0><<<dim3(3 * HID / 32, HID / 32), 256>>>(W_qkv, HID, 3 * HID);
    transpose_tf32_kernel<1><<<dim3(HID / 32, HID / 32), 256>>>(W_dense, HID, HID);

    // 1) QKV projection (tensor tf32), scatter head-major
    tc_gemm<0><<<dim3(3 * HID / 128, S_LEN / 128), 256>>>(b_qkv, nullptr, HID, 3 * HID);

    // 2) causal flash attention (fp32) -> g_ctx (tf32-rounded)
    attn_kernel<<<dim3(32, 16), 256, ATTN_SMEM>>>();

    // 3) dense projection (tensor tf32)
    tc_gemm<1><<<dim3(HID / 128, S_LEN / 128), 256>>>(b_dense, out, HID, HID);
}

// round 4
// speedup vs baseline: 2.8862x; 1.6890x over previous
#include <cuda_runtime.h>
#include <math.h>
#include <float.h>
#include <stdint.h>

#define S_LEN 2048
#define HID   2048
#define NHEAD 16
#define HS    128

// ---- scratch (no cudaMalloc allowed) ----
__device__ float g_q[NHEAD * S_LEN * HS];
__device__ float g_k[NHEAD * S_LEN * HS];
__device__ float g_v[NHEAD * S_LEN * HS];
__device__ float g_ctx[S_LEN * HID];          // tf32-rounded fp32
__device__ float g_a[S_LEN * HID];            // hidden, tf32-rounded
__device__ float g_wt_qkv[3 * HID * HID];     // W_qkv^T  [6144, 2048] tf32
__device__ float g_wt_dense[HID * HID];       // W_dense^T [2048, 2048] tf32

__device__ __forceinline__ float to_tf32(float x) {
    float r; asm("cvt.rna.tf32.f32 %0, %1;" : "=f"(r) : "f"(x)); return r;
}

// m16n8k8 tf32 mma (sm_80+ legacy path; valid on PTX target sm_103)
__device__ __forceinline__ void mma_tf32(float* d, const uint32_t* a,
                                         const uint32_t* b, const float* c) {
    asm volatile(
        "mma.sync.aligned.m16n8k8.row.col.f32.tf32.tf32.f32 "
        "{%0, %1, %2, %3}, {%4, %5, %6, %7}, {%8, %9}, {%10, %11, %12, %13};"
        : "=f"(d[0]), "=f"(d[1]), "=f"(d[2]), "=f"(d[3])
        : "r"(a[0]), "r"(a[1]), "r"(a[2]), "r"(a[3]),
          "r"(b[0]), "r"(b[1]),
          "f"(c[0]), "f"(c[1]), "f"(c[2]), "f"(c[3]));
}

// =====================================================================
// prep kernels
// =====================================================================
__global__ void __launch_bounds__(256) cvt_tf32_kernel(const float* __restrict__ in) {
    int i = blockIdx.x * blockDim.x + threadIdx.x;
    float4 v = ((const float4*)in)[i];
    v.x = to_tf32(v.x); v.y = to_tf32(v.y); v.z = to_tf32(v.z); v.w = to_tf32(v.w);
    ((float4*)g_a)[i] = v;
}

// W [K, N] fp32 -> Wt [N, K] tf32
template<int WHICH>
__global__ void __launch_bounds__(256) transpose_tf32_kernel(const float* __restrict__ W,
                                                             int K, int N) {
    __shared__ float t[32][33];
    float* Wt = (WHICH == 0) ? g_wt_qkv : g_wt_dense;
    int n0 = blockIdx.x * 32, k0 = blockIdx.y * 32;
    int tx = threadIdx.x & 31, ty = threadIdx.x >> 5;
#pragma unroll
    for (int i = 0; i < 32; i += 8)
        t[ty + i][tx] = W[(size_t)(k0 + ty + i) * N + n0 + tx];
    __syncthreads();
#pragma unroll
    for (int i = 0; i < 32; i += 8)
        Wt[(size_t)(n0 + ty + i) * K + k0 + tx] = to_tf32(t[tx][ty + i]);
}

// =====================================================================
// tf32 tensor GEMM via mma.sync (unchanged from R3 passing version)
// =====================================================================
#define SMS 36

template<int MODE>
__global__ void __launch_bounds__(256)
tc_gemm(const float* __restrict__ bias, float* __restrict__ C, int K, int N)
{
    __shared__ float As[128 * SMS];
    __shared__ float Bs[128 * SMS];

    const float* A  = (MODE == 0) ? g_a : g_ctx;
    const float* Bt = (MODE == 0) ? g_wt_qkv : g_wt_dense;

    int tid  = threadIdx.x;
    int lane = tid & 31, wid = tid >> 5;
    int bcol = blockIdx.x * 128;
    int brow = blockIdx.y * 128;
    int wm = (wid >> 2) * 64;
    int wn = (wid & 3) * 32;

    int g = lane >> 2;
    int t = lane & 3;

    float acc[4][4][4];
#pragma unroll
    for (int mt = 0; mt < 4; mt++)
#pragma unroll
        for (int nt = 0; nt < 4; nt++)
#pragma unroll
            for (int r = 0; r < 4; r++) acc[mt][nt][r] = 0.f;

    for (int k0 = 0; k0 < K; k0 += 32) {
#pragma unroll
        for (int it = 0; it < 4; it++) {
            int idx = tid + it * 256;
            int row = idx >> 3;
            int c4  = (idx & 7) << 2;
            *(float4*)&As[row * SMS + c4] =
                *(const float4*)(A + (size_t)(brow + row) * K + k0 + c4);
            *(float4*)&Bs[row * SMS + c4] =
                *(const float4*)(Bt + (size_t)(bcol + row) * K + k0 + c4);
        }
        __syncthreads();

#pragma unroll
        for (int kk = 0; kk < 32; kk += 8) {
            uint32_t af[4][4], bf[4][2];
#pragma unroll
            for (int mt = 0; mt < 4; mt++) {
                const float* ap = &As[(wm + mt * 16 + g) * SMS + kk + t];
                af[mt][0] = __float_as_uint(ap[0]);
                af[mt][1] = __float_as_uint(ap[8 * SMS]);
                af[mt][2] = __float_as_uint(ap[4]);
                af[mt][3] = __float_as_uint(ap[8 * SMS + 4]);
            }
#pragma unroll
            for (int nt = 0; nt < 4; nt++) {
                const float* bp = &Bs[(wn + nt * 8 + g) * SMS + kk + t];
                bf[nt][0] = __float_as_uint(bp[0]);
                bf[nt][1] = __float_as_uint(bp[4]);
            }
#pragma unroll
            for (int mt = 0; mt < 4; mt++)
#pragma unroll
                for (int nt = 0; nt < 4; nt++)
                    mma_tf32(acc[mt][nt], af[mt], bf[nt], acc[mt][nt]);
        }
        __syncthreads();
    }

    float* dstbase;
    int ld;
    if (MODE == 0) {
        int kind = bcol >> 11;
        int head = (bcol & 2047) >> 7;
        dstbase = (kind == 0 ? g_q : kind == 1 ? g_k : g_v)
                  + (size_t)head * S_LEN * HS;
        ld = HS;
    } else {
        dstbase = C;
        ld = N;
    }
#pragma unroll
    for (int mt = 0; mt < 4; mt++) {
#pragma unroll
        for (int nt = 0; nt < 4; nt++) {
            int col = wn + nt * 8 + 2 * t;
            int bi  = bcol + col;
            float bx = __ldg(&bias[bi]), by = __ldg(&bias[bi + 1]);
            int r0 = brow + wm + mt * 16 + g;
            int cc = (MODE == 0) ? col : bcol + col;
            float2 v0 = make_float2(acc[mt][nt][0] + bx, acc[mt][nt][1] + by);
            float2 v1 = make_float2(acc[mt][nt][2] + bx, acc[mt][nt][3] + by);
            *(float2*)(dstbase + (size_t)r0 * ld + cc)       = v0;
            *(float2*)(dstbase + (size_t)(r0 + 8) * ld + cc) = v1;
        }
    }
}

// =====================================================================
// Tensorized flash attention (tf32 mma, fp32 softmax), causal.
// Per CTA: 1 head x 128 q-rows. 256 threads = 8 warps x 16 rows.
// Inner loop: K/V tiles of 64 tokens.
// smem: Qs[128][132], Ks[64][132], Vt[128][68] (V^T), Ps[128][68]
// =====================================================================
#define QS_ST 132
#define VT_ST 68

__global__ void __launch_bounds__(256) attn_kernel()
{
    extern __shared__ float sm[];
    float* Qs = sm;                       // 128*132 = 16896
    float* Ks = Qs + 128 * QS_ST;         // 64*132  =  8448
    float* Vt = Ks + 64 * QS_ST;          // 128*68  =  8704
    float* Ps = Vt + 128 * VT_ST;         // 128*68  =  8704

    int tid  = threadIdx.x;
    int lane = tid & 31, wid = tid >> 5;
    int g = lane >> 2, t = lane & 3;

    int qtile = (gridDim.x - 1) - blockIdx.x;   // heavy CTAs first
    int head  = blockIdx.y;
    const float* Qp = g_q + (size_t)head * S_LEN * HS;
    const float* Kp = g_k + (size_t)head * S_LEN * HS;
    const float* Vp = g_v + (size_t)head * S_LEN * HS;

    int q0 = qtile * 128;

    // stage Q (tf32-rounded), row-major stride 132
#pragma unroll
    for (int it = 0; it < 16; it++) {
        int idx = tid + it * 256;            // 0..4095 float4 slots
        int r = idx >> 5;
        int c = (idx & 31) << 2;
        float4 v = *(const float4*)(Qp + (size_t)(q0 + r) * HS + c);
        v.x = to_tf32(v.x); v.y = to_tf32(v.y);
        v.z = to_tf32(v.z); v.w = to_tf32(v.w);
        *(float4*)&Qs[r * QS_ST + c] = v;
    }

    const float scale = 0.08838834764831845f;   // 1/sqrt(128)
    int lr   = wid * 16 + g;                    // local row (and +8)
    int row0 = q0 + lr;

    float m0 = -FLT_MAX, m1 = -FLT_MAX, l0 = 0.f, l1 = 0.f;
    float o[16][4];
#pragma unroll
    for (int nt = 0; nt < 16; nt++)
#pragma unroll
        for (int r = 0; r < 4; r++) o[nt][r] = 0.f;

    int jmax = 2 * qtile + 1;
    for (int jt = 0; jt <= jmax; jt++) {
        int k0 = jt * 64;
        __syncthreads();                        // prior S/PV reads of Ks/Vt done

        // stage K (row-major) and V (transposed), tf32-rounded
#pragma unroll
        for (int it = 0; it < 8; it++) {
            int idx = tid + it * 256;           // 0..2047 float4 slots
            int r = idx >> 5;                   // token 0..63
            int c = (idx & 31) << 2;            // dim
            float4 kv = *(const float4*)(Kp + (size_t)(k0 + r) * HS + c);
            kv.x = to_tf32(kv.x); kv.y = to_tf32(kv.y);
            kv.z = to_tf32(kv.z); kv.w = to_tf32(kv.w);
            *(float4*)&Ks[r * QS_ST + c] = kv;
            float4 vv = *(const float4*)(Vp + (size_t)(k0 + r) * HS + c);
            Vt[(c + 0) * VT_ST + r] = to_tf32(vv.x);
            Vt[(c + 1) * VT_ST + r] = to_tf32(vv.y);
            Vt[(c + 2) * VT_ST + r] = to_tf32(vv.z);
            Vt[(c + 3) * VT_ST + r] = to_tf32(vv.w);
        }
        __syncthreads();

        // ---- S = Q @ K^T : 16 rows x 64 cols per warp ----
        float sacc[8][4];
#pragma unroll
        for (int nt = 0; nt < 8; nt++)
#pragma unroll
            for (int r = 0; r < 4; r++) sacc[nt][r] = 0.f;

#pragma unroll
        for (int kk = 0; kk < 16; kk++) {
            const float* ap = &Qs[lr * QS_ST + kk * 8 + t];
            uint32_t af[4];
            af[0] = __float_as_uint(ap[0]);
            af[1] = __float_as_uint(ap[8 * QS_ST]);
            af[2] = __float_as_uint(ap[4]);
            af[3] = __float_as_uint(ap[8 * QS_ST + 4]);
#pragma unroll
            for (int nt = 0; nt < 8; nt++) {
                const float* bp = &Ks[(nt * 8 + g) * QS_ST + kk * 8 + t];
                uint32_t bf[2];
                bf[0] = __float_as_uint(bp[0]);
                bf[1] = __float_as_uint(bp[4]);
                mma_tf32(sacc[nt], af, bf, sacc[nt]);
            }
        }

        // ---- scale + causal mask + online softmax (registers) ----
        bool diag = (jt >= 2 * qtile);
        float mx0 = -FLT_MAX, mx1 = -FLT_MAX;
#pragma unroll
        for (int nt = 0; nt < 8; nt++) {
            int colb = k0 + nt * 8 + 2 * t;
            float v0 = sacc[nt][0] * scale;
            float v1 = sacc[nt][1] * scale;
            float v2 = sacc[nt][2] * scale;
            float v3 = sacc[nt][3] * scale;
            if (diag) {
                if (colb     > row0)     v0 = -FLT_MAX;
                if (colb + 1 > row0)     v1 = -FLT_MAX;
                if (colb     > row0 + 8) v2 = -FLT_MAX;
                if (colb + 1 > row0 + 8) v3 = -FLT_MAX;
            }
            sacc[nt][0] = v0; sacc[nt][1] = v1;
            sacc[nt][2] = v2; sacc[nt][3] = v3;
            mx0 = fmaxf(mx0, fmaxf(v0, v1));
            mx1 = fmaxf(mx1, fmaxf(v2, v3));
        }
        mx0 = fmaxf(mx0, __shfl_xor_sync(0xffffffffu, mx0, 1));
        mx0 = fmaxf(mx0, __shfl_xor_sync(0xffffffffu, mx0, 2));
        mx1 = fmaxf(mx1, __shfl_xor_sync(0xffffffffu, mx1, 1));
        mx1 = fmaxf(mx1, __shfl_xor_sync(0xffffffffu, mx1, 2));
        float m0n = fmaxf(m0, mx0), m1n = fmaxf(m1, mx1);

        float s0 = 0.f, s1 = 0.f;
#pragma unroll
        for (int nt = 0; nt < 8; nt++) {
            float p0 = __expf(sacc[nt][0] - m0n);
            float p1 = __expf(sacc[nt][1] - m0n);
            float p2 = __expf(sacc[nt][2] - m1n);
            float p3 = __expf(sacc[nt][3] - m1n);
            s0 += p0 + p1;
            s1 += p2 + p3;
            *(float2*)&Ps[lr * VT_ST + nt * 8 + 2 * t] =
                make_float2(to_tf32(p0), to_tf32(p1));
            *(float2*)&Ps[(lr + 8) * VT_ST + nt * 8 + 2 * t] =
                make_float2(to_tf32(p2), to_tf32(p3));
        }
        s0 += __shfl_xor_sync(0xffffffffu, s0, 1);
        s0 += __shfl_xor_sync(0xffffffffu, s0, 2);
        s1 += __shfl_xor_sync(0xffffffffu, s1, 1);
        s1 += __shfl_xor_sync(0xffffffffu, s1, 2);

        float sc0 = __expf(m0 - m0n), sc1 = __expf(m1 - m1n);
        l0 = l0 * sc0 + s0;  l1 = l1 * sc1 + s1;
        m0 = m0n;            m1 = m1n;
#pragma unroll
        for (int nt = 0; nt < 16; nt++) {
            o[nt][0] *= sc0; o[nt][1] *= sc0;
            o[nt][2] *= sc1; o[nt][3] *= sc1;
        }
        __syncwarp();    // Ps rows of this warp visible warp-wide

        // ---- O += P @ V ----
#pragma unroll
        for (int kk = 0; kk < 8; kk++) {
            const float* ap = &Ps[lr * VT_ST + kk * 8 + t];
            uint32_t af[4];
            af[0] = __float_as_uint(ap[0]);
            af[1] = __float_as_uint(ap[8 * VT_ST]);
            af[2] = __float_as_uint(ap[4]);
            af[3] = __float_as_uint(ap[8 * VT_ST + 4]);
#pragma unroll
            for (int nt = 0; nt < 16; nt++) {
                const float* bp = &Vt[(nt * 8 + g) * VT_ST + kk * 8 + t];
                uint32_t bf[2];
                bf[0] = __float_as_uint(bp[0]);
                bf[1] = __float_as_uint(bp[4]);
                mma_tf32(o[nt], af, bf, o[nt]);
            }
        }
    }

    // ---- epilogue: normalize, store to g_ctx (tf32-rounded) ----
    float inv0 = 1.f / l0, inv1 = 1.f / l1;
    float* dst0 = g_ctx + (size_t)row0 * HID + head * HS;
    float* dst1 = dst0 + (size_t)8 * HID;
#pragma unroll
    for (int nt = 0; nt < 16; nt++) {
        int c = nt * 8 + 2 * t;
        *(float2*)(dst0 + c) = make_float2(to_tf32(o[nt][0] * inv0),
                                           to_tf32(o[nt][1] * inv0));
        *(float2*)(dst1 + c) = make_float2(to_tf32(o[nt][2] * inv1),
                                           to_tf32(o[nt][3] * inv1));
    }
}

// =====================================================================
// launch
// =====================================================================
extern "C" void kernel_launch(void* const* d_in, const int* in_sizes, int n_in,
                              void* d_out, int out_size)
{
    const float* hidden  = (const float*)d_in[0];
    // d_in[1] = ltor_mask (always causal tril; handled analytically)
    const float* W_qkv   = (const float*)d_in[2];
    const float* b_qkv   = (const float*)d_in[3];
    const float* W_dense = (const float*)d_in[4];
    const float* b_dense = (const float*)d_in[5];
    float* out = (float*)d_out;

    const int ATTN_SMEM = (128 * QS_ST + 64 * QS_ST + 128 * VT_ST + 128 * VT_ST)
                          * (int)sizeof(float);   // 171008 B
    cudaFuncSetAttribute(attn_kernel,
                         cudaFuncAttributeMaxDynamicSharedMemorySize, ATTN_SMEM);

    // prep: tf32-round activations; transpose+round weights
    cvt_tf32_kernel<<<(S_LEN * HID / 4) / 256, 256>>>(hidden);
    transpose_tf32_kernel<0><<<dim3(3 * HID / 32, HID / 32), 256>>>(W_qkv, HID, 3 * HID);
    transpose_tf32_kernel<1><<<dim3(HID / 32, HID / 32), 256>>>(W_dense, HID, HID);

    // 1) QKV projection (tensor tf32), scatter head-major
    tc_gemm<0><<<dim3(3 * HID / 128, S_LEN / 128), 256>>>(b_qkv, nullptr, HID, 3 * HID);

    // 2) causal flash attention (tensor tf32) -> g_ctx
    attn_kernel<<<dim3(16, 16), 256, ATTN_SMEM>>>();

    // 3) dense projection (tensor tf32)
    tc_gemm<1><<<dim3(HID / 128, S_LEN / 128), 256>>>(b_dense, out, HID, HID);
}

// round 5
// speedup vs baseline: 3.1037x; 1.0754x over previous
#include <cuda_runtime.h>
#include <math.h>
#include <float.h>
#include <stdint.h>

#define S_LEN 2048
#define HID   2048
#define NHEAD 16
#define HS    128

// ---- scratch (no cudaMalloc allowed) ----
__device__ float g_q[NHEAD * S_LEN * HS];
__device__ float g_k[NHEAD * S_LEN * HS];
__device__ float g_v[NHEAD * S_LEN * HS];
__device__ float g_ctx[S_LEN * HID];          // tf32-rounded fp32
__device__ float g_a[S_LEN * HID];            // hidden, tf32-rounded
__device__ float g_wt_qkv[3 * HID * HID];     // W_qkv^T  [6144, 2048] tf32
__device__ float g_wt_dense[HID * HID];       // W_dense^T [2048, 2048] tf32

__device__ __forceinline__ float to_tf32(float x) {
    float r; asm("cvt.rna.tf32.f32 %0, %1;" : "=f"(r) : "f"(x)); return r;
}

// m16n8k8 tf32 mma (sm_80+ legacy path; valid on PTX target sm_103)
__device__ __forceinline__ void mma_tf32(float* d, const uint32_t* a,
                                         const uint32_t* b, const float* c) {
    asm volatile(
        "mma.sync.aligned.m16n8k8.row.col.f32.tf32.tf32.f32 "
        "{%0, %1, %2, %3}, {%4, %5, %6, %7}, {%8, %9}, {%10, %11, %12, %13};"
        : "=f"(d[0]), "=f"(d[1]), "=f"(d[2]), "=f"(d[3])
        : "r"(a[0]), "r"(a[1]), "r"(a[2]), "r"(a[3]),
          "r"(b[0]), "r"(b[1]),
          "f"(c[0]), "f"(c[1]), "f"(c[2]), "f"(c[3]));
}

__device__ __forceinline__ void cp_async16(uint32_t smem, const void* g) {
    asm volatile("cp.async.cg.shared.global [%0], [%1], 16;"
                 :: "r"(smem), "l"(g) : "memory");
}

// =====================================================================
// prep kernels
// =====================================================================
__global__ void __launch_bounds__(256) cvt_tf32_kernel(const float* __restrict__ in) {
    int i = blockIdx.x * blockDim.x + threadIdx.x;
    float4 v = ((const float4*)in)[i];
    v.x = to_tf32(v.x); v.y = to_tf32(v.y); v.z = to_tf32(v.z); v.w = to_tf32(v.w);
    ((float4*)g_a)[i] = v;
}

// W [K, N] fp32 -> Wt [N, K] tf32
template<int WHICH>
__global__ void __launch_bounds__(256) transpose_tf32_kernel(const float* __restrict__ W,
                                                             int K, int N) {
    __shared__ float t[32][33];
    float* Wt = (WHICH == 0) ? g_wt_qkv : g_wt_dense;
    int n0 = blockIdx.x * 32, k0 = blockIdx.y * 32;
    int tx = threadIdx.x & 31, ty = threadIdx.x >> 5;
#pragma unroll
    for (int i = 0; i < 32; i += 8)
        t[ty + i][tx] = W[(size_t)(k0 + ty + i) * N + n0 + tx];
    __syncthreads();
#pragma unroll
    for (int i = 0; i < 32; i += 8)
        Wt[(size_t)(n0 + ty + i) * K + k0 + tx] = to_tf32(t[tx][ty + i]);
}

// =====================================================================
// tf32 tensor GEMM, 3-stage cp.async pipeline.
// block 128x128x32, 256 thr (8 warps 2x4), warp tile 64x32 (4x4 m16n8k8)
// =====================================================================
#define SMS 36
#define STAGES 3
#define STG_FLOATS (128 * SMS)
#define GEMM_SMEM (STAGES * 2 * STG_FLOATS * (int)sizeof(float))

template<int MODE>
__global__ void __launch_bounds__(256)
tc_gemm(const float* __restrict__ bias, float* __restrict__ C, int K, int N)
{
    extern __shared__ float smem[];
    float* As = smem;                          // [STAGES][128*SMS]
    float* Bs = smem + STAGES * STG_FLOATS;

    const float* A  = (MODE == 0) ? g_a : g_ctx;
    const float* Bt = (MODE == 0) ? g_wt_qkv : g_wt_dense;

    int tid  = threadIdx.x;
    int lane = tid & 31, wid = tid >> 5;
    int bcol = blockIdx.x * 128;
    int brow = blockIdx.y * 128;
    int wm = (wid >> 2) * 64;
    int wn = (wid & 3) * 32;

    int g = lane >> 2;
    int t = lane & 3;

    float acc[4][4][4];
#pragma unroll
    for (int mt = 0; mt < 4; mt++)
#pragma unroll
        for (int nt = 0; nt < 4; nt++)
#pragma unroll
            for (int r = 0; r < 4; r++) acc[mt][nt][r] = 0.f;

    // per-thread fixed staging coordinates
    int s_row = tid >> 3;            // 0..31 (x4 batches of 32 rows)
    int s_c4  = (tid & 7) << 2;      // 0,4,...,28

    auto prefetch = [&](int kt, int s) {
        uint32_t a_base = (uint32_t)__cvta_generic_to_shared(&As[s * STG_FLOATS]);
        uint32_t b_base = (uint32_t)__cvta_generic_to_shared(&Bs[s * STG_FLOATS]);
#pragma unroll
        for (int it = 0; it < 4; it++) {
            int row = s_row + it * 32;
            uint32_t so = (uint32_t)(row * SMS + s_c4) * 4u;
            cp_async16(a_base + so, A  + (size_t)(brow + row) * K + kt * 32 + s_c4);
            cp_async16(b_base + so, Bt + (size_t)(bcol + row) * K + kt * 32 + s_c4);
        }
        asm volatile("cp.async.commit_group;" ::: "memory");
    };

    const int NT = K / 32;
    prefetch(0, 0);
    prefetch(1, 1);

    for (int kt = 0; kt < NT; kt++) {
        asm volatile("cp.async.wait_group 1;" ::: "memory");
        __syncthreads();
        if (kt + 2 < NT) prefetch(kt + 2, (kt + 2) % STAGES);

        const float* Asb = &As[(kt % STAGES) * STG_FLOATS];
        const float* Bsb = &Bs[(kt % STAGES) * STG_FLOATS];

#pragma unroll
        for (int kk = 0; kk < 32; kk += 8) {
            uint32_t af[4][4], bf[4][2];
#pragma unroll
            for (int mt = 0; mt < 4; mt++) {
                const float* ap = &Asb[(wm + mt * 16 + g) * SMS + kk + t];
                af[mt][0] = __float_as_uint(ap[0]);
                af[mt][1] = __float_as_uint(ap[8 * SMS]);
                af[mt][2] = __float_as_uint(ap[4]);
                af[mt][3] = __float_as_uint(ap[8 * SMS + 4]);
            }
#pragma unroll
            for (int nt = 0; nt < 4; nt++) {
                const float* bp = &Bsb[(wn + nt * 8 + g) * SMS + kk + t];
                bf[nt][0] = __float_as_uint(bp[0]);
                bf[nt][1] = __float_as_uint(bp[4]);
            }
#pragma unroll
            for (int mt = 0; mt < 4; mt++)
#pragma unroll
                for (int nt = 0; nt < 4; nt++)
                    mma_tf32(acc[mt][nt], af[mt], bf[nt], acc[mt][nt]);
        }
        __syncthreads();
    }

    float* dstbase;
    int ld;
    if (MODE == 0) {
        int kind = bcol >> 11;
        int head = (bcol & 2047) >> 7;
        dstbase = (kind == 0 ? g_q : kind == 1 ? g_k : g_v)
                  + (size_t)head * S_LEN * HS;
        ld = HS;
    } else {
        dstbase = C;
        ld = N;
    }
#pragma unroll
    for (int mt = 0; mt < 4; mt++) {
#pragma unroll
        for (int nt = 0; nt < 4; nt++) {
            int col = wn + nt * 8 + 2 * t;
            int bi  = bcol + col;
            float bx = __ldg(&bias[bi]), by = __ldg(&bias[bi + 1]);
            int r0 = brow + wm + mt * 16 + g;
            int cc = (MODE == 0) ? col : bcol + col;
            float2 v0 = make_float2(acc[mt][nt][0] + bx, acc[mt][nt][1] + by);
            float2 v1 = make_float2(acc[mt][nt][2] + bx, acc[mt][nt][3] + by);
            *(float2*)(dstbase + (size_t)r0 * ld + cc)       = v0;
            *(float2*)(dstbase + (size_t)(r0 + 8) * ld + cc) = v1;
        }
    }
}

// =====================================================================
// Tensorized flash attention (tf32 mma, fp32 softmax), causal.
// (unchanged from R4 passing version)
// =====================================================================
#define QS_ST 132
#define VT_ST 68

__global__ void __launch_bounds__(256) attn_kernel()
{
    extern __shared__ float sm[];
    float* Qs = sm;
    float* Ks = Qs + 128 * QS_ST;
    float* Vt = Ks + 64 * QS_ST;
    float* Ps = Vt + 128 * VT_ST;

    int tid  = threadIdx.x;
    int lane = tid & 31, wid = tid >> 5;
    int g = lane >> 2, t = lane & 3;

    int qtile = (gridDim.x - 1) - blockIdx.x;
    int head  = blockIdx.y;
    const float* Qp = g_q + (size_t)head * S_LEN * HS;
    const float* Kp = g_k + (size_t)head * S_LEN * HS;
    const float* Vp = g_v + (size_t)head * S_LEN * HS;

    int q0 = qtile * 128;

#pragma unroll
    for (int it = 0; it < 16; it++) {
        int idx = tid + it * 256;
        int r = idx >> 5;
        int c = (idx & 31) << 2;
        float4 v = *(const float4*)(Qp + (size_t)(q0 + r) * HS + c);
        v.x = to_tf32(v.x); v.y = to_tf32(v.y);
        v.z = to_tf32(v.z); v.w = to_tf32(v.w);
        *(float4*)&Qs[r * QS_ST + c] = v;
    }

    const float scale = 0.08838834764831845f;
    int lr   = wid * 16 + g;
    int row0 = q0 + lr;

    float m0 = -FLT_MAX, m1 = -FLT_MAX, l0 = 0.f, l1 = 0.f;
    float o[16][4];
#pragma unroll
    for (int nt = 0; nt < 16; nt++)
#pragma unroll
        for (int r = 0; r < 4; r++) o[nt][r] = 0.f;

    int jmax = 2 * qtile + 1;
    for (int jt = 0; jt <= jmax; jt++) {
        int k0 = jt * 64;
        __syncthreads();

#pragma unroll
        for (int it = 0; it < 8; it++) {
            int idx = tid + it * 256;
            int r = idx >> 5;
            int c = (idx & 31) << 2;
            float4 kv = *(const float4*)(Kp + (size_t)(k0 + r) * HS + c);
            kv.x = to_tf32(kv.x); kv.y = to_tf32(kv.y);
            kv.z = to_tf32(kv.z); kv.w = to_tf32(kv.w);
            *(float4*)&Ks[r * QS_ST + c] = kv;
            float4 vv = *(const float4*)(Vp + (size_t)(k0 + r) * HS + c);
            Vt[(c + 0) * VT_ST + r] = to_tf32(vv.x);
            Vt[(c + 1) * VT_ST + r] = to_tf32(vv.y);
            Vt[(c + 2) * VT_ST + r] = to_tf32(vv.z);
            Vt[(c + 3) * VT_ST + r] = to_tf32(vv.w);
        }
        __syncthreads();

        float sacc[8][4];
#pragma unroll
        for (int nt = 0; nt < 8; nt++)
#pragma unroll
            for (int r = 0; r < 4; r++) sacc[nt][r] = 0.f;

#pragma unroll
        for (int kk = 0; kk < 16; kk++) {
            const float* ap = &Qs[lr * QS_ST + kk * 8 + t];
            uint32_t af[4];
            af[0] = __float_as_uint(ap[0]);
            af[1] = __float_as_uint(ap[8 * QS_ST]);
            af[2] = __float_as_uint(ap[4]);
            af[3] = __float_as_uint(ap[8 * QS_ST + 4]);
#pragma unroll
            for (int nt = 0; nt < 8; nt++) {
                const float* bp = &Ks[(nt * 8 + g) * QS_ST + kk * 8 + t];
                uint32_t bf[2];
                bf[0] = __float_as_uint(bp[0]);
                bf[1] = __float_as_uint(bp[4]);
                mma_tf32(sacc[nt], af, bf, sacc[nt]);
            }
        }

        bool diag = (jt >= 2 * qtile);
        float mx0 = -FLT_MAX, mx1 = -FLT_MAX;
#pragma unroll
        for (int nt = 0; nt < 8; nt++) {
            int colb = k0 + nt * 8 + 2 * t;
            float v0 = sacc[nt][0] * scale;
            float v1 = sacc[nt][1] * scale;
            float v2 = sacc[nt][2] * scale;
            float v3 = sacc[nt][3] * scale;
            if (diag) {
                if (colb     > row0)     v0 = -FLT_MAX;
                if (colb + 1 > row0)     v1 = -FLT_MAX;
                if (colb     > row0 + 8) v2 = -FLT_MAX;
                if (colb + 1 > row0 + 8) v3 = -FLT_MAX;
            }
            sacc[nt][0] = v0; sacc[nt][1] = v1;
            sacc[nt][2] = v2; sacc[nt][3] = v3;
            mx0 = fmaxf(mx0, fmaxf(v0, v1));
            mx1 = fmaxf(mx1, fmaxf(v2, v3));
        }
        mx0 = fmaxf(mx0, __shfl_xor_sync(0xffffffffu, mx0, 1));
        mx0 = fmaxf(mx0, __shfl_xor_sync(0xffffffffu, mx0, 2));
        mx1 = fmaxf(mx1, __shfl_xor_sync(0xffffffffu, mx1, 1));
        mx1 = fmaxf(mx1, __shfl_xor_sync(0xffffffffu, mx1, 2));
        float m0n = fmaxf(m0, mx0), m1n = fmaxf(m1, mx1);

        float s0 = 0.f, s1 = 0.f;
#pragma unroll
        for (int nt = 0; nt < 8; nt++) {
            float p0 = __expf(sacc[nt][0] - m0n);
            float p1 = __expf(sacc[nt][1] - m0n);
            float p2 = __expf(sacc[nt][2] - m1n);
            float p3 = __expf(sacc[nt][3] - m1n);
            s0 += p0 + p1;
            s1 += p2 + p3;
            *(float2*)&Ps[lr * VT_ST + nt * 8 + 2 * t] =
                make_float2(to_tf32(p0), to_tf32(p1));
            *(float2*)&Ps[(lr + 8) * VT_ST + nt * 8 + 2 * t] =
                make_float2(to_tf32(p2), to_tf32(p3));
        }
        s0 += __shfl_xor_sync(0xffffffffu, s0, 1);
        s0 += __shfl_xor_sync(0xffffffffu, s0, 2);
        s1 += __shfl_xor_sync(0xffffffffu, s1, 1);
        s1 += __shfl_xor_sync(0xffffffffu, s1, 2);

        float sc0 = __expf(m0 - m0n), sc1 = __expf(m1 - m1n);
        l0 = l0 * sc0 + s0;  l1 = l1 * sc1 + s1;
        m0 = m0n;            m1 = m1n;
#pragma unroll
        for (int nt = 0; nt < 16; nt++) {
            o[nt][0] *= sc0; o[nt][1] *= sc0;
            o[nt][2] *= sc1; o[nt][3] *= sc1;
        }
        __syncwarp();

#pragma unroll
        for (int kk = 0; kk < 8; kk++) {
            const float* ap = &Ps[lr * VT_ST + kk * 8 + t];
            uint32_t af[4];
            af[0] = __float_as_uint(ap[0]);
            af[1] = __float_as_uint(ap[8 * VT_ST]);
            af[2] = __float_as_uint(ap[4]);
            af[3] = __float_as_uint(ap[8 * VT_ST + 4]);
#pragma unroll
            for (int nt = 0; nt < 16; nt++) {
                const float* bp = &Vt[(nt * 8 + g) * VT_ST + kk * 8 + t];
                uint32_t bf[2];
                bf[0] = __float_as_uint(bp[0]);
                bf[1] = __float_as_uint(bp[4]);
                mma_tf32(o[nt], af, bf, o[nt]);
            }
        }
    }

    float inv0 = 1.f / l0, inv1 = 1.f / l1;
    float* dst0 = g_ctx + (size_t)row0 * HID + head * HS;
    float* dst1 = dst0 + (size_t)8 * HID;
#pragma unroll
    for (int nt = 0; nt < 16; nt++) {
        int c = nt * 8 + 2 * t;
        *(float2*)(dst0 + c) = make_float2(to_tf32(o[nt][0] * inv0),
                                           to_tf32(o[nt][1] * inv0));
        *(float2*)(dst1 + c) = make_float2(to_tf32(o[nt][2] * inv1),
                                           to_tf32(o[nt][3] * inv1));
    }
}

// =====================================================================
// launch
// =====================================================================
extern "C" void kernel_launch(void* const* d_in, const int* in_sizes, int n_in,
                              void* d_out, int out_size)
{
    const float* hidden  = (const float*)d_in[0];
    // d_in[1] = ltor_mask (always causal tril; handled analytically)
    const float* W_qkv   = (const float*)d_in[2];
    const float* b_qkv   = (const float*)d_in[3];
    const float* W_dense = (const float*)d_in[4];
    const float* b_dense = (const float*)d_in[5];
    float* out = (float*)d_out;

    const int ATTN_SMEM = (128 * QS_ST + 64 * QS_ST + 128 * VT_ST + 128 * VT_ST)
                          * (int)sizeof(float);
    cudaFuncSetAttribute(attn_kernel,
                         cudaFuncAttributeMaxDynamicSharedMemorySize, ATTN_SMEM);
    cudaFuncSetAttribute(tc_gemm<0>,
                         cudaFuncAttributeMaxDynamicSharedMemorySize, GEMM_SMEM);
    cudaFuncSetAttribute(tc_gemm<1>,
                         cudaFuncAttributeMaxDynamicSharedMemorySize, GEMM_SMEM);

    // prep: tf32-round activations; transpose+round weights
    cvt_tf32_kernel<<<(S_LEN * HID / 4) / 256, 256>>>(hidden);
    transpose_tf32_kernel<0><<<dim3(3 * HID / 32, HID / 32), 256>>>(W_qkv, HID, 3 * HID);
    transpose_tf32_kernel<1><<<dim3(HID / 32, HID / 32), 256>>>(W_dense, HID, HID);

    // 1) QKV projection (tensor tf32, cp.async pipelined), scatter head-major
    tc_gemm<0><<<dim3(3 * HID / 128, S_LEN / 128), 256, GEMM_SMEM>>>(b_qkv, nullptr,
                                                                     HID, 3 * HID);
    // 2) causal flash attention (tensor tf32) -> g_ctx
    attn_kernel<<<dim3(16, 16), 256, ATTN_SMEM>>>();

    // 3) dense projection (tensor tf32, cp.async pipelined)
    tc_gemm<1><<<dim3(HID / 128, S_LEN / 128), 256, GEMM_SMEM>>>(b_dense, out,
                                                                 HID, HID);
}

// round 7
// speedup vs baseline: 4.4596x; 1.4369x over previous
#include <cuda_runtime.h>
#include <cuda_fp16.h>
#include <math.h>
#include <float.h>
#include <stdint.h>

#define S_LEN 2048
#define HID   2048
#define NHEAD 16
#define HS    128

// ---- scratch (no cudaMalloc allowed) ----
__device__ __half g_q[NHEAD * S_LEN * HS];
__device__ __half g_k[NHEAD * S_LEN * HS];
__device__ __half g_v[NHEAD * S_LEN * HS];
__device__ __half g_ctx[S_LEN * HID];
__device__ __half g_a[S_LEN * HID];            // hidden, fp16
__device__ __half g_wt_qkv[3 * HID * HID];     // W_qkv^T  [6144, 2048] fp16
__device__ __half g_wt_dense[HID * HID];       // W_dense^T [2048, 2048] fp16

// m16n8k16 fp16 mma, fp32 accumulate
__device__ __forceinline__ void mma_f16(float* d, const uint32_t* a,
                                        const uint32_t* b, const float* c) {
    asm volatile(
        "mma.sync.aligned.m16n8k16.row.col.f32.f16.f16.f32 "
        "{%0, %1, %2, %3}, {%4, %5, %6, %7}, {%8, %9}, {%10, %11, %12, %13};"
        : "=f"(d[0]), "=f"(d[1]), "=f"(d[2]), "=f"(d[3])
        : "r"(a[0]), "r"(a[1]), "r"(a[2]), "r"(a[3]),
          "r"(b[0]), "r"(b[1]),
          "f"(c[0]), "f"(c[1]), "f"(c[2]), "f"(c[3]));
}

__device__ __forceinline__ void cp_async16(uint32_t smem, const void* g) {
    asm volatile("cp.async.cg.shared.global [%0], [%1], 16;"
                 :: "r"(smem), "l"(g) : "memory");
}
__device__ __forceinline__ uint32_t ld_h2(const __half* p) {
    return *(const uint32_t*)p;
}

// =====================================================================
// prep kernels
// =====================================================================
__global__ void __launch_bounds__(256) cvt_half_kernel(const float* __restrict__ in) {
    int i = blockIdx.x * blockDim.x + threadIdx.x;   // 8-float group
    float4 v0 = ((const float4*)in)[2 * i];
    float4 v1 = ((const float4*)in)[2 * i + 1];
    __half2 h[4];
    h[0] = __floats2half2_rn(v0.x, v0.y);
    h[1] = __floats2half2_rn(v0.z, v0.w);
    h[2] = __floats2half2_rn(v1.x, v1.y);
    h[3] = __floats2half2_rn(v1.z, v1.w);
    ((uint2*)g_a)[2 * i]     = make_uint2(*(uint32_t*)&h[0], *(uint32_t*)&h[1]);
    ((uint2*)g_a)[2 * i + 1] = make_uint2(*(uint32_t*)&h[2], *(uint32_t*)&h[3]);
}

// W [K, N] fp32 -> Wt [N, K] fp16
template<int WHICH>
__global__ void __launch_bounds__(256) transpose_half_kernel(const float* __restrict__ W,
                                                             int K, int N) {
    __shared__ float t[32][33];
    __half* Wt = (WHICH == 0) ? g_wt_qkv : g_wt_dense;
    int n0 = blockIdx.x * 32, k0 = blockIdx.y * 32;
    int tx = threadIdx.x & 31, ty = threadIdx.x >> 5;
#pragma unroll
    for (int i = 0; i < 32; i += 8)
        t[ty + i][tx] = W[(size_t)(k0 + ty + i) * N + n0 + tx];
    __syncthreads();
#pragma unroll
    for (int i = 0; i < 32; i += 8)
        Wt[(size_t)(n0 + ty + i) * K + k0 + tx] = __float2half(t[tx][ty + i]);
}

// =====================================================================
// fp16 tensor GEMM, 3-stage cp.async pipeline.
// block 128x128x32, 256 thr (8 warps 2x4), warp tile 64x32 (4x2 m16n8k16)
// smem stride 40 halfs -> conflict-free fragment LDS (word=20g+t distinct)
// =====================================================================
#define ST2 40
#define STAGES 3
#define STG_HALFS (128 * ST2)
#define GEMM_SMEM (STAGES * 2 * STG_HALFS * (int)sizeof(__half))

template<int MODE>
__global__ void __launch_bounds__(256)
tc_gemm(const float* __restrict__ bias, float* __restrict__ C, int K, int N)
{
    extern __shared__ __half smh[];
    __half* As = smh;                           // [STAGES][128*ST2]
    __half* Bs = smh + STAGES * STG_HALFS;

    const __half* A  = (MODE == 0) ? g_a : g_ctx;
    const __half* Bt = (MODE == 0) ? g_wt_qkv : g_wt_dense;

    int tid  = threadIdx.x;
    int lane = tid & 31, wid = tid >> 5;
    int bcol = blockIdx.x * 128;
    int brow = blockIdx.y * 128;
    int wm = (wid >> 2) * 64;
    int wn = (wid & 3) * 32;

    int g = lane >> 2;
    int t = lane & 3;

    float acc[4][4][4];
#pragma unroll
    for (int mt = 0; mt < 4; mt++)
#pragma unroll
        for (int nt = 0; nt < 4; nt++)
#pragma unroll
            for (int r = 0; r < 4; r++) acc[mt][nt][r] = 0.f;

    // staging: per matrix 128 rows x 32 halfs = 512 x 16B chunks
    int s_row = tid >> 2;            // 0..63 (+64)
    int s_c8  = (tid & 3) << 3;      // 0,8,16,24

    auto prefetch = [&](int kt, int s) {
        uint32_t a_base = (uint32_t)__cvta_generic_to_shared(&As[s * STG_HALFS]);
        uint32_t b_base = (uint32_t)__cvta_generic_to_shared(&Bs[s * STG_HALFS]);
#pragma unroll
        for (int it = 0; it < 2; it++) {
            int row = s_row + it * 64;
            uint32_t so = (uint32_t)(row * ST2 + s_c8) * 2u;
            cp_async16(a_base + so, A  + (size_t)(brow + row) * K + kt * 32 + s_c8);
            cp_async16(b_base + so, Bt + (size_t)(bcol + row) * K + kt * 32 + s_c8);
        }
        asm volatile("cp.async.commit_group;" ::: "memory");
    };

    const int NT = K / 32;
    prefetch(0, 0);
    prefetch(1, 1);

    for (int kt = 0; kt < NT; kt++) {
        asm volatile("cp.async.wait_group 1;" ::: "memory");
        __syncthreads();
        if (kt + 2 < NT) prefetch(kt + 2, (kt + 2) % STAGES);

        const __half* Asb = &As[(kt % STAGES) * STG_HALFS];
        const __half* Bsb = &Bs[(kt % STAGES) * STG_HALFS];

#pragma unroll
        for (int kk = 0; kk < 2; kk++) {          // 2 x K=16
            uint32_t af[4][4], bf[4][2];
#pragma unroll
            for (int mt = 0; mt < 4; mt++) {
                const __half* ap = &Asb[(wm + mt * 16 + g) * ST2 + kk * 16 + 2 * t];
                af[mt][0] = ld_h2(ap);
                af[mt][1] = ld_h2(ap + 8 * ST2);
                af[mt][2] = ld_h2(ap + 8);
                af[mt][3] = ld_h2(ap + 8 * ST2 + 8);
            }
#pragma unroll
            for (int nt = 0; nt < 4; nt++) {
                const __half* bp = &Bsb[(wn + nt * 8 + g) * ST2 + kk * 16 + 2 * t];
                bf[nt][0] = ld_h2(bp);
                bf[nt][1] = ld_h2(bp + 8);
            }
#pragma unroll
            for (int mt = 0; mt < 4; mt++)
#pragma unroll
                for (int nt = 0; nt < 4; nt++)
                    mma_f16(acc[mt][nt], af[mt], bf[nt], acc[mt][nt]);
        }
    }

    // ---- epilogue ----
    if (MODE == 0) {
        int kind = bcol >> 11;
        int head = (bcol & 2047) >> 7;
        __half* dstbase = (kind == 0 ? g_q : kind == 1 ? g_k : g_v)
                          + (size_t)head * S_LEN * HS;
#pragma unroll
        for (int mt = 0; mt < 4; mt++) {
#pragma unroll
            for (int nt = 0; nt < 4; nt++) {
                int col = wn + nt * 8 + 2 * t;    // within-head column
                int bi  = bcol + col;
                float bx = __ldg(&bias[bi]), by = __ldg(&bias[bi + 1]);
                int r0 = brow + wm + mt * 16 + g;
                __half2 v0 = __floats2half2_rn(acc[mt][nt][0] + bx, acc[mt][nt][1] + by);
                __half2 v1 = __floats2half2_rn(acc[mt][nt][2] + bx, acc[mt][nt][3] + by);
                *(__half2*)(dstbase + (size_t)r0 * HS + col)       = v0;
                *(__half2*)(dstbase + (size_t)(r0 + 8) * HS + col) = v1;
            }
        }
    } else {
#pragma unroll
        for (int mt = 0; mt < 4; mt++) {
#pragma unroll
            for (int nt = 0; nt < 4; nt++) {
                int col = bcol + wn + nt * 8 + 2 * t;
                float bx = __ldg(&bias[col]), by = __ldg(&bias[col + 1]);
                int r0 = brow + wm + mt * 16 + g;
                float2 v0 = make_float2(acc[mt][nt][0] + bx, acc[mt][nt][1] + by);
                float2 v1 = make_float2(acc[mt][nt][2] + bx, acc[mt][nt][3] + by);
                *(float2*)(C + (size_t)r0 * N + col)       = v0;
                *(float2*)(C + (size_t)(r0 + 8) * N + col) = v1;
            }
        }
    }
}

// =====================================================================
// fp16 tensorized flash attention (fp32 softmax/accum), causal.
// Per CTA: 1 head x 128 q-rows. 256 threads = 8 warps x 16 rows.
// smem (halfs): Qs[128][136], Ks[64][136], Vt[128][72], Ps[128][72]
// =====================================================================
#define QS2 136
#define VT2 72

__global__ void __launch_bounds__(256) attn_kernel()
{
    extern __shared__ __half smha[];
    __half* Qs = smha;                        // 128*136
    __half* Ks = Qs + 128 * QS2;              // 64*136
    __half* Vt = Ks + 64 * QS2;               // 128*72
    __half* Ps = Vt + 128 * VT2;              // 128*72

    int tid  = threadIdx.x;
    int lane = tid & 31, wid = tid >> 5;
    int g = lane >> 2, t = lane & 3;

    int qtile = (gridDim.x - 1) - blockIdx.x;   // heavy CTAs first
    int head  = blockIdx.y;
    const __half* Qp = g_q + (size_t)head * S_LEN * HS;
    const __half* Kp = g_k + (size_t)head * S_LEN * HS;
    const __half* Vp = g_v + (size_t)head * S_LEN * HS;

    int q0 = qtile * 128;

    // stage Q: 128x128 halfs = 2048 uint4 (8 halfs each)
#pragma unroll
    for (int it = 0; it < 8; it++) {
        int idx = tid + it * 256;
        int r  = idx >> 4;
        int c8 = (idx & 15) << 3;
        *(uint4*)&Qs[r * QS2 + c8] = *(const uint4*)(Qp + (size_t)(q0 + r) * HS + c8);
    }

    const float scale = 0.08838834764831845f;   // 1/sqrt(128)
    int lr   = wid * 16 + g;
    int row0 = q0 + lr;

    float m0 = -FLT_MAX, m1 = -FLT_MAX, l0 = 0.f, l1 = 0.f;
    float o[16][4];
#pragma unroll
    for (int nt = 0; nt < 16; nt++)
#pragma unroll
        for (int r = 0; r < 4; r++) o[nt][r] = 0.f;

    int jmax = 2 * qtile + 1;
    for (int jt = 0; jt <= jmax; jt++) {
        int k0 = jt * 64;
        __syncthreads();                        // prior S/PV reads done

        // stage K (row-major) and V (transposed)
#pragma unroll
        for (int it = 0; it < 4; it++) {
            int idx = tid + it * 256;           // 0..1023
            int r  = idx >> 4;                  // token 0..63
            int c8 = (idx & 15) << 3;
            *(uint4*)&Ks[r * QS2 + c8] = *(const uint4*)(Kp + (size_t)(k0 + r) * HS + c8);
            uint4 vv = *(const uint4*)(Vp + (size_t)(k0 + r) * HS + c8);
            const __half* vh = (const __half*)&vv;
#pragma unroll
            for (int j = 0; j < 8; j++)
                Vt[(c8 + j) * VT2 + r] = vh[j];
        }
        __syncthreads();

        // ---- S = Q @ K^T : 16 rows x 64 cols per warp ----
        float sacc[8][4];
#pragma unroll
        for (int nt = 0; nt < 8; nt++)
#pragma unroll
            for (int r = 0; r < 4; r++) sacc[nt][r] = 0.f;

#pragma unroll
        for (int kk = 0; kk < 8; kk++) {        // 8 x K=16
            const __half* ap = &Qs[lr * QS2 + kk * 16 + 2 * t];
            uint32_t af[4];
            af[0] = ld_h2(ap);
            af[1] = ld_h2(ap + 8 * QS2);
            af[2] = ld_h2(ap + 8);
            af[3] = ld_h2(ap + 8 * QS2 + 8);
#pragma unroll
            for (int nt = 0; nt < 8; nt++) {
                const __half* bp = &Ks[(nt * 8 + g) * QS2 + kk * 16 + 2 * t];
                uint32_t bf[2];
                bf[0] = ld_h2(bp);
                bf[1] = ld_h2(bp + 8);
                mma_f16(sacc[nt], af, bf, sacc[nt]);
            }
        }

        // ---- scale + causal mask + online softmax ----
        bool diag = (jt >= 2 * qtile);
        float mx0 = -FLT_MAX, mx1 = -FLT_MAX;
#pragma unroll
        for (int nt = 0; nt < 8; nt++) {
            int colb = k0 + nt * 8 + 2 * t;
            float v0 = sacc[nt][0] * scale;
            float v1 = sacc[nt][1] * scale;
            float v2 = sacc[nt][2] * scale;
            float v3 = sacc[nt][3] * scale;
            if (diag) {
                if (colb     > row0)     v0 = -FLT_MAX;
                if (colb + 1 > row0)     v1 = -FLT_MAX;
                if (colb     > row0 + 8) v2 = -FLT_MAX;
                if (colb + 1 > row0 + 8) v3 = -FLT_MAX;
            }
            sacc[nt][0] = v0; sacc[nt][1] = v1;
            sacc[nt][2] = v2; sacc[nt][3] = v3;
            mx0 = fmaxf(mx0, fmaxf(v0, v1));
            mx1 = fmaxf(mx1, fmaxf(v2, v3));
        }
        mx0 = fmaxf(mx0, __shfl_xor_sync(0xffffffffu, mx0, 1));
        mx0 = fmaxf(mx0, __shfl_xor_sync(0xffffffffu, mx0, 2));
        mx1 = fmaxf(mx1, __shfl_xor_sync(0xffffffffu, mx1, 1));
        mx1 = fmaxf(mx1, __shfl_xor_sync(0xffffffffu, mx1, 2));
        float m0n = fmaxf(m0, mx0), m1n = fmaxf(m1, mx1);

        float s0 = 0.f, s1 = 0.f;
#pragma unroll
        for (int nt = 0; nt < 8; nt++) {
            float p0 = __expf(sacc[nt][0] - m0n);
            float p1 = __expf(sacc[nt][1] - m0n);
            float p2 = __expf(sacc[nt][2] - m1n);
            float p3 = __expf(sacc[nt][3] - m1n);
            s0 += p0 + p1;
            s1 += p2 + p3;
            *(__half2*)&Ps[lr * VT2 + nt * 8 + 2 * t]       = __floats2half2_rn(p0, p1);
            *(__half2*)&Ps[(lr + 8) * VT2 + nt * 8 + 2 * t] = __floats2half2_rn(p2, p3);
        }
        s0 += __shfl_xor_sync(0xffffffffu, s0, 1);
        s0 += __shfl_xor_sync(0xffffffffu, s0, 2);
        s1 += __shfl_xor_sync(0xffffffffu, s1, 1);
        s1 += __shfl_xor_sync(0xffffffffu, s1, 2);

        float sc0 = __expf(m0 - m0n), sc1 = __expf(m1 - m1n);
        l0 = l0 * sc0 + s0;  l1 = l1 * sc1 + s1;
        m0 = m0n;            m1 = m1n;
#pragma unroll
        for (int nt = 0; nt < 16; nt++) {
            o[nt][0] *= sc0; o[nt][1] *= sc0;
            o[nt][2] *= sc1; o[nt][3] *= sc1;
        }
        __syncwarp();    // Ps rows of this warp visible warp-wide

        // ---- O += P @ V ----
#pragma unroll
        for (int kk = 0; kk < 4; kk++) {        // 4 x K=16 over 64 tokens
            const __half* ap = &Ps[lr * VT2 + kk * 16 + 2 * t];
            uint32_t af[4];
            af[0] = ld_h2(ap);
            af[1] = ld_h2(ap + 8 * VT2);
            af[2] = ld_h2(ap + 8);
            af[3] = ld_h2(ap + 8 * VT2 + 8);
#pragma unroll
            for (int nt = 0; nt < 16; nt++) {
                const __half* bp = &Vt[(nt * 8 + g) * VT2 + kk * 16 + 2 * t];
                uint32_t bf[2];
                bf[0] = ld_h2(bp);
                bf[1] = ld_h2(bp + 8);
                mma_f16(o[nt], af, bf, o[nt]);
            }
        }
    }

    // ---- epilogue: normalize, store to g_ctx (fp16) ----
    float inv0 = 1.f / l0, inv1 = 1.f / l1;
    __half* dst0 = g_ctx + (size_t)row0 * HID + head * HS;
    __half* dst1 = dst0 + (size_t)8 * HID;
#pragma unroll
    for (int nt = 0; nt < 16; nt++) {
        int c = nt * 8 + 2 * t;
        *(__half2*)(dst0 + c) = __floats2half2_rn(o[nt][0] * inv0, o[nt][1] * inv0);
        *(__half2*)(dst1 + c) = __floats2half2_rn(o[nt][2] * inv1, o[nt][3] * inv1);
    }
}

// =====================================================================
// launch
// =====================================================================
extern "C" void kernel_launch(void* const* d_in, const int* in_sizes, int n_in,
                              void* d_out, int out_size)
{
    const float* hidden  = (const float*)d_in[0];
    // d_in[1] = ltor_mask (always causal tril; handled analytically)
    const float* W_qkv   = (const float*)d_in[2];
    const float* b_qkv   = (const float*)d_in[3];
    const float* W_dense = (const float*)d_in[4];
    const float* b_dense = (const float*)d_in[5];
    float* out = (float*)d_out;

    const int ATTN_SMEM = (128 * QS2 + 64 * QS2 + 128 * VT2 + 128 * VT2)
                          * (int)sizeof(__half);   // 89088 B
    cudaFuncSetAttribute(attn_kernel,
                         cudaFuncAttributeMaxDynamicSharedMemorySize, ATTN_SMEM);
    cudaFuncSetAttribute(tc_gemm<0>,
                         cudaFuncAttributeMaxDynamicSharedMemorySize, GEMM_SMEM);
    cudaFuncSetAttribute(tc_gemm<1>,
                         cudaFuncAttributeMaxDynamicSharedMemorySize, GEMM_SMEM);

    // prep: fp16 conversions
    cvt_half_kernel<<<(S_LEN * HID / 8) / 256, 256>>>(hidden);
    transpose_half_kernel<0><<<dim3(3 * HID / 32, HID / 32), 256>>>(W_qkv, HID, 3 * HID);
    transpose_half_kernel<1><<<dim3(HID / 32, HID / 32), 256>>>(W_dense, HID, HID);

    // 1) QKV projection (fp16 tensor, cp.async pipelined), scatter head-major
    tc_gemm<0><<<dim3(3 * HID / 128, S_LEN / 128), 256, GEMM_SMEM>>>(b_qkv, nullptr,
                                                                     HID, 3 * HID);
    // 2) causal flash attention (fp16 tensor) -> g_ctx
    attn_kernel<<<dim3(16, 16), 256, ATTN_SMEM>>>();

    // 3) dense projection (fp16 tensor, cp.async pipelined)
    tc_gemm<1><<<dim3(HID / 128, S_LEN / 128), 256, GEMM_SMEM>>>(b_dense, out,
                                                                 HID, HID);
}

// round 8
// speedup vs baseline: 6.2518x; 1.4019x over previous
#include <cuda_runtime.h>
#include <cuda_fp16.h>
#include <math.h>
#include <float.h>
#include <stdint.h>

#define S_LEN 2048
#define HID   2048
#define NHEAD 16
#define HS    128

// ---- scratch (no cudaMalloc allowed) ----
__device__ __half g_q[NHEAD * S_LEN * HS];
__device__ __half g_k[NHEAD * S_LEN * HS];
__device__ __half g_v[NHEAD * S_LEN * HS];
__device__ __half g_ctx[S_LEN * HID];
__device__ __half g_a[S_LEN * HID];            // hidden, fp16
__device__ __half g_wt_qkv[3 * HID * HID];     // W_qkv^T  [6144, 2048] fp16
__device__ __half g_wt_dense[HID * HID];       // W_dense^T [2048, 2048] fp16

// m16n8k16 fp16 mma, fp32 accumulate
__device__ __forceinline__ void mma_f16(float* d, const uint32_t* a,
                                        const uint32_t* b, const float* c) {
    asm volatile(
        "mma.sync.aligned.m16n8k16.row.col.f32.f16.f16.f32 "
        "{%0, %1, %2, %3}, {%4, %5, %6, %7}, {%8, %9}, {%10, %11, %12, %13};"
        : "=f"(d[0]), "=f"(d[1]), "=f"(d[2]), "=f"(d[3])
        : "r"(a[0]), "r"(a[1]), "r"(a[2]), "r"(a[3]),
          "r"(b[0]), "r"(b[1]),
          "f"(c[0]), "f"(c[1]), "f"(c[2]), "f"(c[3]));
}

__device__ __forceinline__ void ldsm_x4(uint32_t* r, uint32_t addr) {
    asm volatile("ldmatrix.sync.aligned.m8n8.x4.shared.b16 {%0, %1, %2, %3}, [%4];"
                 : "=r"(r[0]), "=r"(r[1]), "=r"(r[2]), "=r"(r[3]) : "r"(addr));
}
__device__ __forceinline__ void ldsm_x4t(uint32_t* r, uint32_t addr) {
    asm volatile("ldmatrix.sync.aligned.m8n8.x4.trans.shared.b16 {%0, %1, %2, %3}, [%4];"
                 : "=r"(r[0]), "=r"(r[1]), "=r"(r[2]), "=r"(r[3]) : "r"(addr));
}
__device__ __forceinline__ void cp_async16(uint32_t smem, const void* g) {
    asm volatile("cp.async.cg.shared.global [%0], [%1], 16;"
                 :: "r"(smem), "l"(g) : "memory");
}

// =====================================================================
// prep kernels
// =====================================================================
__global__ void __launch_bounds__(256) cvt_half_kernel(const float* __restrict__ in) {
    int i = blockIdx.x * blockDim.x + threadIdx.x;   // 8-float group
    float4 v0 = ((const float4*)in)[2 * i];
    float4 v1 = ((const float4*)in)[2 * i + 1];
    __half2 h[4];
    h[0] = __floats2half2_rn(v0.x, v0.y);
    h[1] = __floats2half2_rn(v0.z, v0.w);
    h[2] = __floats2half2_rn(v1.x, v1.y);
    h[3] = __floats2half2_rn(v1.z, v1.w);
    ((uint2*)g_a)[2 * i]     = make_uint2(*(uint32_t*)&h[0], *(uint32_t*)&h[1]);
    ((uint2*)g_a)[2 * i + 1] = make_uint2(*(uint32_t*)&h[2], *(uint32_t*)&h[3]);
}

// W [K, N] fp32 -> Wt [N, K] fp16
template<int WHICH>
__global__ void __launch_bounds__(256) transpose_half_kernel(const float* __restrict__ W,
                                                             int K, int N) {
    __shared__ float t[32][33];
    __half* Wt = (WHICH == 0) ? g_wt_qkv : g_wt_dense;
    int n0 = blockIdx.x * 32, k0 = blockIdx.y * 32;
    int tx = threadIdx.x & 31, ty = threadIdx.x >> 5;
#pragma unroll
    for (int i = 0; i < 32; i += 8)
        t[ty + i][tx] = W[(size_t)(k0 + ty + i) * N + n0 + tx];
    __syncthreads();
#pragma unroll
    for (int i = 0; i < 32; i += 8)
        Wt[(size_t)(n0 + ty + i) * K + k0 + tx] = __float2half(t[tx][ty + i]);
}

// =====================================================================
// fp16 tensor GEMM, 3-stage cp.async pipeline + ldmatrix fragments.
// block 128x128x32, 256 thr (8 warps 2x4), warp tile 64x32 (4x2 m16n8k16)
// smem stride 40 halfs -> conflict-free LDSM (word = row*20 mod 32 distinct)
// =====================================================================
#define ST2 40
#define STAGES 3
#define STG_HALFS (128 * ST2)
#define GEMM_SMEM (STAGES * 2 * STG_HALFS * (int)sizeof(__half))

template<int MODE>
__global__ void __launch_bounds__(256)
tc_gemm(const float* __restrict__ bias, float* __restrict__ C, int K, int N)
{
    extern __shared__ __half smh[];
    __half* As = smh;                           // [STAGES][128*ST2]
    __half* Bs = smh + STAGES * STG_HALFS;

    const __half* A  = (MODE == 0) ? g_a : g_ctx;
    const __half* Bt = (MODE == 0) ? g_wt_qkv : g_wt_dense;

    int tid  = threadIdx.x;
    int lane = tid & 31, wid = tid >> 5;
    int bcol = blockIdx.x * 128;
    int brow = blockIdx.y * 128;
    int wm = (wid >> 2) * 64;
    int wn = (wid & 3) * 32;

    int g = lane >> 2;
    int t = lane & 3;
    int lm = lane & 7;              // row within 8x8 matrix
    int lq = (lane >> 3) & 1;
    int lh = lane >> 4;

    float acc[4][4][4];
#pragma unroll
    for (int mt = 0; mt < 4; mt++)
#pragma unroll
        for (int nt = 0; nt < 4; nt++)
#pragma unroll
            for (int r = 0; r < 4; r++) acc[mt][nt][r] = 0.f;

    // ldmatrix lane offsets (bytes), relative to stage base
    // A x4: m0 rows+0/k0, m1 rows+8/k0, m2 rows+0/k8, m3 rows+8/k8
    uint32_t a_lane_off = (uint32_t)((wm + lm + lq * 8) * ST2 + lh * 8) * 2u;
    // B x4 (two n-tiles): m0 nt rows/k0, m1 nt rows/k8, m2 nt+1 rows/k0, m3 nt+1/k8
    uint32_t b_lane_off = (uint32_t)((wn + lm + lh * 8) * ST2 + lq * 8) * 2u;

    // staging: per matrix 128 rows x 32 halfs = 512 x 16B chunks
    int s_row = tid >> 2;            // 0..63 (+64)
    int s_c8  = (tid & 3) << 3;      // 0,8,16,24

    auto prefetch = [&](int kt, int s) {
        uint32_t a_base = (uint32_t)__cvta_generic_to_shared(&As[s * STG_HALFS]);
        uint32_t b_base = (uint32_t)__cvta_generic_to_shared(&Bs[s * STG_HALFS]);
#pragma unroll
        for (int it = 0; it < 2; it++) {
            int row = s_row + it * 64;
            uint32_t so = (uint32_t)(row * ST2 + s_c8) * 2u;
            cp_async16(a_base + so, A  + (size_t)(brow + row) * K + kt * 32 + s_c8);
            cp_async16(b_base + so, Bt + (size_t)(bcol + row) * K + kt * 32 + s_c8);
        }
        asm volatile("cp.async.commit_group;" ::: "memory");
    };

    const int NT = K / 32;
    prefetch(0, 0);
    prefetch(1, 1);

    for (int kt = 0; kt < NT; kt++) {
        asm volatile("cp.async.wait_group 1;" ::: "memory");
        __syncthreads();
        if (kt + 2 < NT) prefetch(kt + 2, (kt + 2) % STAGES);

        uint32_t a_s = (uint32_t)__cvta_generic_to_shared(
                           &As[(kt % STAGES) * STG_HALFS]) + a_lane_off;
        uint32_t b_s = (uint32_t)__cvta_generic_to_shared(
                           &Bs[(kt % STAGES) * STG_HALFS]) + b_lane_off;

#pragma unroll
        for (int kk = 0; kk < 2; kk++) {          // 2 x K=16
            uint32_t af[4][4], bf[4][2];
#pragma unroll
            for (int mt = 0; mt < 4; mt++)
                ldsm_x4(af[mt], a_s + (uint32_t)(mt * 16 * ST2 + kk * 16) * 2u);
#pragma unroll
            for (int np = 0; np < 2; np++) {      // covers nt = 2np, 2np+1
                uint32_t br[4];
                ldsm_x4(br, b_s + (uint32_t)(np * 16 * ST2 + kk * 16) * 2u);
                bf[2 * np][0]     = br[0];
                bf[2 * np][1]     = br[1];
                bf[2 * np + 1][0] = br[2];
                bf[2 * np + 1][1] = br[3];
            }
#pragma unroll
            for (int mt = 0; mt < 4; mt++)
#pragma unroll
                for (int nt = 0; nt < 4; nt++)
                    mma_f16(acc[mt][nt], af[mt], bf[nt], acc[mt][nt]);
        }
    }

    // ---- epilogue ----
    if (MODE == 0) {
        int kind = bcol >> 11;
        int head = (bcol & 2047) >> 7;
        __half* dstbase = (kind == 0 ? g_q : kind == 1 ? g_k : g_v)
                          + (size_t)head * S_LEN * HS;
#pragma unroll
        for (int mt = 0; mt < 4; mt++) {
#pragma unroll
            for (int nt = 0; nt < 4; nt++) {
                int col = wn + nt * 8 + 2 * t;    // within-head column
                int bi  = bcol + col;
                float bx = __ldg(&bias[bi]), by = __ldg(&bias[bi + 1]);
                int r0 = brow + wm + mt * 16 + g;
                __half2 v0 = __floats2half2_rn(acc[mt][nt][0] + bx, acc[mt][nt][1] + by);
                __half2 v1 = __floats2half2_rn(acc[mt][nt][2] + bx, acc[mt][nt][3] + by);
                *(__half2*)(dstbase + (size_t)r0 * HS + col)       = v0;
                *(__half2*)(dstbase + (size_t)(r0 + 8) * HS + col) = v1;
            }
        }
    } else {
#pragma unroll
        for (int mt = 0; mt < 4; mt++) {
#pragma unroll
            for (int nt = 0; nt < 4; nt++) {
                int col = bcol + wn + nt * 8 + 2 * t;
                float bx = __ldg(&bias[col]), by = __ldg(&bias[col + 1]);
                int r0 = brow + wm + mt * 16 + g;
                float2 v0 = make_float2(acc[mt][nt][0] + bx, acc[mt][nt][1] + by);
                float2 v1 = make_float2(acc[mt][nt][2] + bx, acc[mt][nt][3] + by);
                *(float2*)(C + (size_t)r0 * N + col)       = v0;
                *(float2*)(C + (size_t)(r0 + 8) * N + col) = v1;
            }
        }
    }
}

// =====================================================================
// fp16 tensorized flash attention + ldmatrix, causal, fp32 softmax.
// Per CTA: 1 head x 128 q-rows. 256 threads = 8 warps x 16 rows.
// smem (halfs): Qs[128][136], Ks[64][136], Vs[64][136] (row-major,
//               read via ldmatrix.trans), Ps[128][72]
// =====================================================================
#define QS2 136
#define PS2 72

__global__ void __launch_bounds__(256) attn_kernel()
{
    extern __shared__ __half smha[];
    __half* Qs = smha;                        // 128*136
    __half* Ks = Qs + 128 * QS2;              // 64*136
    __half* Vs = Ks + 64 * QS2;               // 64*136
    __half* Ps = Vs + 64 * QS2;               // 128*72

    int tid  = threadIdx.x;
    int lane = tid & 31, wid = tid >> 5;
    int g = lane >> 2, t = lane & 3;
    int lm = lane & 7;
    int lq = (lane >> 3) & 1;
    int lh = lane >> 4;

    int qtile = (gridDim.x - 1) - blockIdx.x;   // heavy CTAs first
    int head  = blockIdx.y;
    const __half* Qp = g_q + (size_t)head * S_LEN * HS;
    const __half* Kp = g_k + (size_t)head * S_LEN * HS;
    const __half* Vp = g_v + (size_t)head * S_LEN * HS;

    int q0 = qtile * 128;

    // stage Q: 128x128 halfs = 2048 uint4
#pragma unroll
    for (int it = 0; it < 8; it++) {
        int idx = tid + it * 256;
        int r  = idx >> 4;
        int c8 = (idx & 15) << 3;
        *(uint4*)&Qs[r * QS2 + c8] = *(const uint4*)(Qp + (size_t)(q0 + r) * HS + c8);
    }

    const float scale = 0.08838834764831845f;   // 1/sqrt(128)
    int lr   = wid * 16 + g;
    int row0 = q0 + lr;

    // ldmatrix lane base offsets (bytes)
    uint32_t qs_base = (uint32_t)__cvta_generic_to_shared(Qs)
                     + (uint32_t)((wid * 16 + lm + lq * 8) * QS2 + lh * 8) * 2u;
    uint32_t ks_base = (uint32_t)__cvta_generic_to_shared(Ks)
                     + (uint32_t)((lm + lh * 8) * QS2 + lq * 8) * 2u;
    // V trans x4: m0 tok+0/dim0, m1 tok+8/dim0, m2 tok+0/dim8, m3 tok+8/dim8
    uint32_t vs_base = (uint32_t)__cvta_generic_to_shared(Vs)
                     + (uint32_t)((lm + lq * 8) * QS2 + lh * 8) * 2u;
    uint32_t ps_base = (uint32_t)__cvta_generic_to_shared(Ps)
                     + (uint32_t)((wid * 16 + lm + lq * 8) * PS2 + lh * 8) * 2u;

    float m0 = -FLT_MAX, m1 = -FLT_MAX, l0 = 0.f, l1 = 0.f;
    float o[16][4];
#pragma unroll
    for (int nt = 0; nt < 16; nt++)
#pragma unroll
        for (int r = 0; r < 4; r++) o[nt][r] = 0.f;

    int jmax = 2 * qtile + 1;
    for (int jt = 0; jt <= jmax; jt++) {
        int k0 = jt * 64;
        __syncthreads();                        // prior S/PV reads done

        // stage K and V (both row-major)
#pragma unroll
        for (int it = 0; it < 4; it++) {
            int idx = tid + it * 256;           // 0..1023
            int r  = idx >> 4;                  // token 0..63
            int c8 = (idx & 15) << 3;
            *(uint4*)&Ks[r * QS2 + c8] = *(const uint4*)(Kp + (size_t)(k0 + r) * HS + c8);
            *(uint4*)&Vs[r * QS2 + c8] = *(const uint4*)(Vp + (size_t)(k0 + r) * HS + c8);
        }
        __syncthreads();

        // ---- S = Q @ K^T : 16 rows x 64 cols per warp ----
        float sacc[8][4];
#pragma unroll
        for (int nt = 0; nt < 8; nt++)
#pragma unroll
            for (int r = 0; r < 4; r++) sacc[nt][r] = 0.f;

#pragma unroll
        for (int kk = 0; kk < 8; kk++) {        // 8 x K=16
            uint32_t af[4];
            ldsm_x4(af, qs_base + (uint32_t)(kk * 16) * 2u);
#pragma unroll
            for (int np = 0; np < 4; np++) {    // covers nt = 2np, 2np+1
                uint32_t br[4];
                ldsm_x4(br, ks_base + (uint32_t)(np * 16 * QS2 + kk * 16) * 2u);
                mma_f16(sacc[2 * np],     af, &br[0], sacc[2 * np]);
                mma_f16(sacc[2 * np + 1], af, &br[2], sacc[2 * np + 1]);
            }
        }

        // ---- scale + causal mask + online softmax ----
        bool diag = (jt >= 2 * qtile);
        float mx0 = -FLT_MAX, mx1 = -FLT_MAX;
#pragma unroll
        for (int nt = 0; nt < 8; nt++) {
            int colb = k0 + nt * 8 + 2 * t;
            float v0 = sacc[nt][0] * scale;
            float v1 = sacc[nt][1] * scale;
            float v2 = sacc[nt][2] * scale;
            float v3 = sacc[nt][3] * scale;
            if (diag) {
                if (colb     > row0)     v0 = -FLT_MAX;
                if (colb + 1 > row0)     v1 = -FLT_MAX;
                if (colb     > row0 + 8) v2 = -FLT_MAX;
                if (colb + 1 > row0 + 8) v3 = -FLT_MAX;
            }
            sacc[nt][0] = v0; sacc[nt][1] = v1;
            sacc[nt][2] = v2; sacc[nt][3] = v3;
            mx0 = fmaxf(mx0, fmaxf(v0, v1));
            mx1 = fmaxf(mx1, fmaxf(v2, v3));
        }
        mx0 = fmaxf(mx0, __shfl_xor_sync(0xffffffffu, mx0, 1));
        mx0 = fmaxf(mx0, __shfl_xor_sync(0xffffffffu, mx0, 2));
        mx1 = fmaxf(mx1, __shfl_xor_sync(0xffffffffu, mx1, 1));
        mx1 = fmaxf(mx1, __shfl_xor_sync(0xffffffffu, mx1, 2));
        float m0n = fmaxf(m0, mx0), m1n = fmaxf(m1, mx1);

        float s0 = 0.f, s1 = 0.f;
#pragma unroll
        for (int nt = 0; nt < 8; nt++) {
            float p0 = __expf(sacc[nt][0] - m0n);
            float p1 = __expf(sacc[nt][1] - m0n);
            float p2 = __expf(sacc[nt][2] - m1n);
            float p3 = __expf(sacc[nt][3] - m1n);
            s0 += p0 + p1;
            s1 += p2 + p3;
            *(__half2*)&Ps[lr * PS2 + nt * 8 + 2 * t]       = __floats2half2_rn(p0, p1);
            *(__half2*)&Ps[(lr + 8) * PS2 + nt * 8 + 2 * t] = __floats2half2_rn(p2, p3);
        }
        s0 += __shfl_xor_sync(0xffffffffu, s0, 1);
        s0 += __shfl_xor_sync(0xffffffffu, s0, 2);
        s1 += __shfl_xor_sync(0xffffffffu, s1, 1);
        s1 += __shfl_xor_sync(0xffffffffu, s1, 2);

        float sc0 = __expf(m0 - m0n), sc1 = __expf(m1 - m1n);
        l0 = l0 * sc0 + s0;  l1 = l1 * sc1 + s1;
        m0 = m0n;            m1 = m1n;
#pragma unroll
        for (int nt = 0; nt < 16; nt++) {
            o[nt][0] *= sc0; o[nt][1] *= sc0;
            o[nt][2] *= sc1; o[nt][3] *= sc1;
        }
        __syncwarp();    // Ps rows of this warp visible warp-wide

        // ---- O += P @ V ----
#pragma unroll
        for (int kk = 0; kk < 4; kk++) {        // 4 x K=16 over 64 tokens
            uint32_t af[4];
            ldsm_x4(af, ps_base + (uint32_t)(kk * 16) * 2u);
#pragma unroll
            for (int np = 0; np < 8; np++) {    // covers nt = 2np, 2np+1
                uint32_t br[4];
                ldsm_x4t(br, vs_base + (uint32_t)(kk * 16 * QS2 + np * 16) * 2u);
                mma_f16(o[2 * np],     af, &br[0], o[2 * np]);
                mma_f16(o[2 * np + 1], af, &br[2], o[2 * np + 1]);
            }
        }
    }

    // ---- epilogue: normalize, store to g_ctx (fp16) ----
    float inv0 = 1.f / l0, inv1 = 1.f / l1;
    __half* dst0 = g_ctx + (size_t)row0 * HID + head * HS;
    __half* dst1 = dst0 + (size_t)8 * HID;
#pragma unroll
    for (int nt = 0; nt < 16; nt++) {
        int c = nt * 8 + 2 * t;
        *(__half2*)(dst0 + c) = __floats2half2_rn(o[nt][0] * inv0, o[nt][1] * inv0);
        *(__half2*)(dst1 + c) = __floats2half2_rn(o[nt][2] * inv1, o[nt][3] * inv1);
    }
}

// =====================================================================
// launch
// =====================================================================
extern "C" void kernel_launch(void* const* d_in, const int* in_sizes, int n_in,
                              void* d_out, int out_size)
{
    const float* hidden  = (const float*)d_in[0];
    // d_in[1] = ltor_mask (always causal tril; handled analytically)
    const float* W_qkv   = (const float*)d_in[2];
    const float* b_qkv   = (const float*)d_in[3];
    const float* W_dense = (const float*)d_in[4];
    const float* b_dense = (const float*)d_in[5];
    float* out = (float*)d_out;

    const int ATTN_SMEM = (128 * QS2 + 64 * QS2 + 64 * QS2 + 128 * PS2)
                          * (int)sizeof(__half);   // 88064 B
    cudaFuncSetAttribute(attn_kernel,
                         cudaFuncAttributeMaxDynamicSharedMemorySize, ATTN_SMEM);
    cudaFuncSetAttribute(tc_gemm<0>,
                         cudaFuncAttributeMaxDynamicSharedMemorySize, GEMM_SMEM);
    cudaFuncSetAttribute(tc_gemm<1>,
                         cudaFuncAttributeMaxDynamicSharedMemorySize, GEMM_SMEM);

    // prep: fp16 conversions
    cvt_half_kernel<<<(S_LEN * HID / 8) / 256, 256>>>(hidden);
    transpose_half_kernel<0><<<dim3(3 * HID / 32, HID / 32), 256>>>(W_qkv, HID, 3 * HID);
    transpose_half_kernel<1><<<dim3(HID / 32, HID / 32), 256>>>(W_dense, HID, HID);

    // 1) QKV projection (fp16 tensor + ldmatrix), scatter head-major
    tc_gemm<0><<<dim3(3 * HID / 128, S_LEN / 128), 256, GEMM_SMEM>>>(b_qkv, nullptr,
                                                                     HID, 3 * HID);
    // 2) causal flash attention (fp16 tensor + ldmatrix) -> g_ctx
    attn_kernel<<<dim3(16, 16), 256, ATTN_SMEM>>>();

    // 3) dense projection (fp16 tensor + ldmatrix)
    tc_gemm<1><<<dim3(HID / 128, S_LEN / 128), 256, GEMM_SMEM>>>(b_dense, out,
                                                                 HID, HID);
}